// round 9
// baseline (speedup 1.0000x reference)
#include <cuda_runtime.h>
#include <cuda_bf16.h>
#include <cuda_fp16.h>
#include <math.h>

#define FULLM 0xffffffffu

// Problem constants (fixed by setup_inputs)
#define BB 32
#define NN1 1024
#define F0 7
#define KNN 30
#define C1 64
#define RR 64
#define SS 16
#define PP 55
#define CH 256
#define KF 384   // 6*64

// ---------------- scratch (static device globals; no runtime alloc) ----------------
__device__ int    g_nbr[BB*NN1*KNN];
__device__ float  g_t1p[BB*NN1*8];          // t1 padded to 8 floats
__device__ float  g_out[BB*NN1*C1];
__device__ __half g_outh[BB*NN1*C1];        // fp16 copy for byte-capped gathers
__device__ float  g_Y[BB*NN1*C1];
__device__ float  g_M1[BB*32*4096];
__device__ float  g_Vreeb[BB*RR*C1];
__device__ float  g_xkr[BB*RR*KF];
__device__ float  g_outr[BB*RR*CH];
__device__ float  g_Yr[BB*RR*CH];
__device__ float  g_Vfps[BB*PP*C1];
__device__ float  g_Lfps[BB*PP*PP];
__device__ float  g_xkf[BB*PP*KF];
__device__ float  g_outf[BB*PP*CH];
__device__ float  g_Yf[BB*PP*CH];
__device__ float  g_p1p[256];
__device__ float  g_p2[512];
__device__ float  g_p3[512];

// ---------------- helpers ----------------
__device__ __forceinline__ float block_reduce_sum(float v){
    __shared__ float sh[32];
    int lane = threadIdx.x & 31, w = threadIdx.x >> 5;
    #pragma unroll
    for (int o = 16; o; o >>= 1) v += __shfl_down_sync(FULLM, v, o);
    __syncthreads();
    if (lane == 0) sh[w] = v;
    __syncthreads();
    if (threadIdx.x == 0){
        float s = 0.f; int nw = blockDim.x >> 5;
        for (int i = 0; i < nw; i++) s += sh[i];
        return s;
    }
    return 0.f;
}

// ---------------- kNN: warp per row (4 rows/warp), threshold + survivor-compact ----------------
// Also emits t1 = L x (padded to 8 floats).
__global__ __launch_bounds__(256) void k_knn(const float* __restrict__ x, int* __restrict__ nbr){
    __shared__ float xT[F0*NN1];
    __shared__ float sq[NN1];
    __shared__ unsigned skey[8][256];
    __shared__ unsigned short ssid[8][256];
    int b = blockIdx.y;
    int tid = threadIdx.x;
    const float* xb = x + (size_t)b*NN1*F0;
    for (int n = tid; n < NN1; n += 256){
        float s = 0.f;
        #pragma unroll
        for (int f = 0; f < F0; f++){ float v = xb[n*F0+f]; xT[f*NN1+n] = v; s = fmaf(v, v, s); }
        sq[n] = s;
    }
    __syncthreads();
    int warp = tid >> 5, lane = tid & 31;
    unsigned* wk = skey[warp];
    unsigned short* wi = ssid[warp];
    for (int r = 0; r < 4; r++){
        int i = blockIdx.x*32 + warp*4 + r;
        float xi[F0];
        #pragma unroll
        for (int f = 0; f < F0; f++) xi[f] = xT[f*NN1+i];
        float sqi = sq[i];
        unsigned key[32];
        unsigned lmin = 0xFFFFFFFFu;
        #pragma unroll
        for (int t = 0; t < 32; t++){
            int j = t*32 + lane;
            float dot = 0.f;
            #pragma unroll
            for (int f = 0; f < F0; f++) dot = fmaf(xT[f*NN1+j], xi[f], dot);
            float dv = fmaxf(sqi + sq[j] - 2.0f*dot, 0.0f);
            unsigned kk = __float_as_uint(dv);   // monotone for d>=0
            key[t] = kk;
            lmin = min(lmin, kk);
        }
        unsigned thr = __reduce_max_sync(FULLM, lmin);
        unsigned cnt = 0;
        #pragma unroll
        for (int t = 0; t < 32; t++) cnt += (key[t] <= thr) ? 1u : 0u;
        unsigned S = __reduce_add_sync(FULLM, cnt);
        int base = ((b*NN1)+i)*KNN;
        float a_acc = 0.f;
        int myn = 0;
        if (S <= 256u){
            unsigned off = 0;
            #pragma unroll
            for (int t = 0; t < 32; t++){
                bool take = (key[t] <= thr);
                unsigned m = __ballot_sync(FULLM, take);
                if (take){
                    int pos = off + __popc(m & ((1u<<lane)-1u));
                    wk[pos] = key[t];
                    wi[pos] = (unsigned short)(t*32+lane);
                }
                off += __popc(m);
            }
            __syncwarp();
            unsigned sk[8]; unsigned sid[8];
            #pragma unroll
            for (int rr = 0; rr < 8; rr++){
                unsigned p = lane + rr*32;
                if (p < S){ sk[rr] = wk[p]; sid[rr] = wi[p]; }
                else      { sk[rr] = 0xFFFFFFFFu; sid[rr] = 0xFFFFu; }
            }
            unsigned bk = 0xFFFFFFFFu, bi = 0xFFFFFFFFu;
            #pragma unroll
            for (int rr = 0; rr < 8; rr++) if (sk[rr] < bk){ bk = sk[rr]; bi = sid[rr]; }
            for (int it = 0; it < KNN; it++){
                // exact extract-min with lowest-index tie-break: two dependent REDUX
                unsigned win = __reduce_min_sync(FULLM, bk);
                unsigned cand = (bk == win) ? bi : 0xFFFFFFFFu;
                unsigned widx = __reduce_min_sync(FULLM, cand);
                if (lane == it) myn = (int)widx;
                if (lane < F0) a_acc += xT[lane*NN1 + (int)widx];
                if (bk == win && bi == widx){
                    #pragma unroll
                    for (int rr = 0; rr < 8; rr++) if (sid[rr] == (unsigned short)widx) sk[rr] = 0xFFFFFFFFu;
                    bk = 0xFFFFFFFFu; bi = 0xFFFFFFFFu;
                    #pragma unroll
                    for (int rr = 0; rr < 8; rr++) if (sk[rr] < bk){ bk = sk[rr]; bi = sid[rr]; }
                }
            }
        } else {
            for (int it = 0; it < KNN; it++){
                unsigned bk = 0xFFFFFFFFu; int bt = 0;
                #pragma unroll
                for (int t = 0; t < 32; t++) if (key[t] < bk){ bk = key[t]; bt = t; }
                unsigned bi = (unsigned)(bt*32 + lane);
                unsigned win = __reduce_min_sync(FULLM, bk);
                unsigned cand = (bk == win) ? bi : 0xFFFFFFFFu;
                unsigned widx = __reduce_min_sync(FULLM, cand);
                if (lane == it) myn = (int)widx;
                if (lane < F0) a_acc += xT[lane*NN1 + (int)widx];
                if ((widx & 31u) == (unsigned)lane){
                    int slot = (int)(widx >> 5);
                    #pragma unroll
                    for (int t = 0; t < 32; t++) if (t == slot) key[t] = 0xFFFFFFFFu;
                }
            }
        }
        if (lane < KNN) nbr[base + lane] = myn;
        if (lane < 8){
            float v = (lane < F0) ? (xT[lane*NN1+i] - a_acc*(1.0f/30.0f)) : 0.0f;
            g_t1p[((size_t)(b*NN1)+i)*8 + lane] = v;
        }
        __syncwarp();
    }
}

// ---------------- conv1: out = relu([x|t1|t2] @ W1 + b1); also fp16 copy ----------------
__global__ __launch_bounds__(128) void k_conv1(const float* __restrict__ x,
                                               const float* __restrict__ W1,
                                               const float* __restrict__ b1){
    __shared__ float Ws[21*64];
    __shared__ float bs[64];
    for (int i = threadIdx.x; i < 21*64; i += blockDim.x) Ws[i] = W1[i];
    for (int i = threadIdx.x; i < 64; i += blockDim.x) bs[i] = b1[i];
    __syncthreads();
    int id = blockIdx.x*blockDim.x + threadIdx.x;
    int b = id >> 10, n = id & 1023;
    float in[21];
    const float* xr = x + (size_t)id*F0;
    #pragma unroll
    for (int f = 0; f < F0; f++) in[f] = xr[f];
    const float4* t1b4 = (const float4*)(g_t1p + (size_t)b*NN1*8);
    float4 own0 = t1b4[n*2], own1 = t1b4[n*2+1];
    in[7]=own0.x; in[8]=own0.y; in[9]=own0.z; in[10]=own0.w;
    in[11]=own1.x; in[12]=own1.y; in[13]=own1.z;
    float4 ac0 = make_float4(0,0,0,0), ac1 = make_float4(0,0,0,0);
    const int* nb = g_nbr + (size_t)id*KNN;
    #pragma unroll 2
    for (int s = 0; s < KNN; s++){
        int j = nb[s];
        float4 v0 = t1b4[j*2], v1 = t1b4[j*2+1];
        ac0.x += v0.x; ac0.y += v0.y; ac0.z += v0.z; ac0.w += v0.w;
        ac1.x += v1.x; ac1.y += v1.y; ac1.z += v1.z;
    }
    const float inv = 1.0f/30.0f;
    in[14] = 2.0f*(in[7]  - ac0.x*inv) - in[0];
    in[15] = 2.0f*(in[8]  - ac0.y*inv) - in[1];
    in[16] = 2.0f*(in[9]  - ac0.z*inv) - in[2];
    in[17] = 2.0f*(in[10] - ac0.w*inv) - in[3];
    in[18] = 2.0f*(in[11] - ac1.x*inv) - in[4];
    in[19] = 2.0f*(in[12] - ac1.y*inv) - in[5];
    in[20] = 2.0f*(in[13] - ac1.z*inv) - in[6];
    float o[64];
    #pragma unroll
    for (int c = 0; c < 64; c++) o[c] = bs[c];
    #pragma unroll
    for (int f = 0; f < 21; f++){
        float v = in[f];
        #pragma unroll
        for (int c = 0; c < 64; c++) o[c] = fmaf(v, Ws[f*64+c], o[c]);
    }
    float* orow = g_out + (size_t)id*C1;
    __half2* hrow = (__half2*)(g_outh + (size_t)id*C1);
    #pragma unroll
    for (int c = 0; c < 64; c += 2){
        float r0 = fmaxf(o[c], 0.f), r1 = fmaxf(o[c+1], 0.f);
        orow[c] = r0; orow[c+1] = r1;
        hrow[c>>1] = __floats2half2_rn(r0, r1);
    }
}

// ---------------- Y = L @ out (warp per node, fp16 gathers) ----------------
__global__ void k_Yknn(){
    int wid = (blockIdx.x*blockDim.x + threadIdx.x) >> 5;
    int lane = threadIdx.x & 31;
    if (wid >= BB*NN1) return;
    int b = wid >> 10;
    const __half2* ob = (const __half2*)(g_outh + (size_t)b*NN1*C1);
    const int* nb = g_nbr + (size_t)wid*KNN;
    float ax = 0.f, ay = 0.f;
    #pragma unroll 3
    for (int s = 0; s < KNN; s++){
        int j = nb[s];
        float2 f = __half22float2(ob[j*32 + lane]);
        ax += f.x; ay += f.y;
    }
    float2 orow = *(const float2*)(g_out + (size_t)wid*C1 + lane*2);
    float2 y;
    y.x = orow.x - ax*(1.0f/30.0f);
    y.y = orow.y - ay*(1.0f/30.0f);
    *(float2*)(g_Y + (size_t)wid*C1 + lane*2) = y;
}

// ---------------- reg1 phase A: partial M = out^T Y over one 32-row chunk ----------------
__global__ __launch_bounds__(256) void k_reg1a(){
    __shared__ __align__(16) float sA[32*64];
    __shared__ __align__(16) float sB[32*64];
    int c = blockIdx.x, b = blockIdx.y, t = threadIdx.x;
    const float* ob = g_out + (size_t)b*NN1*C1 + (size_t)c*32*64;
    const float* yb = g_Y   + (size_t)b*NN1*C1 + (size_t)c*32*64;
    for (int i = t; i < 2048; i += 256){ sA[i] = ob[i]; sB[i] = yb[i]; }
    __syncthreads();
    int tx = t & 15, ty = t >> 4;
    float acc[4][4] = {};
    #pragma unroll 4
    for (int n = 0; n < 32; n++){
        float a[4];
        #pragma unroll
        for (int u = 0; u < 4; u++) a[u] = sA[n*64 + ty*4 + u];
        float4 bv = *(const float4*)(sB + n*64 + tx*4);
        #pragma unroll
        for (int u = 0; u < 4; u++){
            acc[u][0] = fmaf(a[u], bv.x, acc[u][0]);
            acc[u][1] = fmaf(a[u], bv.y, acc[u][1]);
            acc[u][2] = fmaf(a[u], bv.z, acc[u][2]);
            acc[u][3] = fmaf(a[u], bv.w, acc[u][3]);
        }
    }
    float* mp = g_M1 + ((size_t)b*32 + c)*4096;
    #pragma unroll
    for (int u = 0; u < 4; u++)
        #pragma unroll
        for (int v = 0; v < 4; v++) mp[(ty*4+u)*64 + tx*4 + v] = acc[u][v];
}

// ---------------- reg1 phase B: parallel partial-sum + square ----------------
__global__ __launch_bounds__(256) void k_reg1b(){
    int piece = blockIdx.x, b = blockIdx.y, t = threadIdx.x;
    const float* mp = g_M1 + (size_t)b*32*4096;
    float s = 0.f;
    #pragma unroll
    for (int r = 0; r < 2; r++){
        int e = piece*512 + r*256 + t;
        float v = 0.f;
        #pragma unroll
        for (int c = 0; c < 32; c++) v += mp[c*4096 + e];
        s = fmaf(v, v, s);
    }
    s = block_reduce_sum(s);
    if (t == 0) g_p1p[b*8 + piece] = s;
}

// ---------------- segment max (reeb, fp32), 4 rows per 256-thread block ----------------
__global__ __launch_bounds__(256) void k_vreeb(const int* __restrict__ sccs){
    int r = blockIdx.x*4 + (threadIdx.x >> 6), b = blockIdx.y, f = threadIdx.x & 63;
    const int* sc = sccs + ((size_t)b*RR + r)*SS;
    const float* ob = g_out + (size_t)b*NN1*C1;
    float m = -3.4e38f;
    #pragma unroll 4
    for (int s = 0; s < SS; s++){ int idx = sc[s]; m = fmaxf(m, ob[idx*C1 + f]); }
    g_Vreeb[((size_t)b*RR + r)*C1 + f] = m;
}

// ---------------- segment max (fps): fp16 gathers, uint4 rows ----------------
__global__ __launch_bounds__(256) void k_vfps(const int* __restrict__ sf){
    __shared__ int sidx[1024];
    __shared__ float part[16][64];
    int p = blockIdx.x, b = blockIdx.y, t = threadIdx.x;
    const int4* si4 = (const int4*)(sf + ((size_t)b*PP + p)*NN1);
    ((int4*)sidx)[t] = si4[t];
    __syncthreads();
    const uint4* ob4 = (const uint4*)(g_outh + (size_t)b*NN1*C1);
    int grp = t >> 3, ln = t & 7;
    __half2 m0 = __float2half2_rn(0.f), m1 = m0, m2 = m0, m3 = m0;  // out >= 0 (relu)
    #pragma unroll 4
    for (int i = 0; i < 32; i++){
        int j = sidx[grp + i*32];
        uint4 v = ob4[j*8 + ln];
        m0 = __hmax2(m0, *(__half2*)&v.x);
        m1 = __hmax2(m1, *(__half2*)&v.y);
        m2 = __hmax2(m2, *(__half2*)&v.z);
        m3 = __hmax2(m3, *(__half2*)&v.w);
    }
    float2 f0 = __half22float2(m0), f1 = __half22float2(m1);
    float2 f2 = __half22float2(m2), f3 = __half22float2(m3);
    int slot = grp & 15;
    if (grp < 16){
        float* pr = &part[slot][ln*8];
        pr[0]=f0.x; pr[1]=f0.y; pr[2]=f1.x; pr[3]=f1.y;
        pr[4]=f2.x; pr[5]=f2.y; pr[6]=f3.x; pr[7]=f3.y;
    }
    __syncthreads();
    if (grp >= 16){
        float* pr = &part[slot][ln*8];
        pr[0]=fmaxf(pr[0],f0.x); pr[1]=fmaxf(pr[1],f0.y); pr[2]=fmaxf(pr[2],f1.x); pr[3]=fmaxf(pr[3],f1.y);
        pr[4]=fmaxf(pr[4],f2.x); pr[5]=fmaxf(pr[5],f2.y); pr[6]=fmaxf(pr[6],f3.x); pr[7]=fmaxf(pr[7],f3.y);
    }
    __syncthreads();
    if (t < 64){
        float mm = part[0][t];
        #pragma unroll
        for (int g = 1; g < 16; g++) mm = fmaxf(mm, part[g][t]);
        g_Vfps[((size_t)b*PP + p)*C1 + t] = mm;
    }
}

// ---------------- L_fps from pairwise distances of V_fps ----------------
__global__ __launch_bounds__(256) void k_Lfps(){
    __shared__ float Vs[PP*64];
    __shared__ float sqs[64];
    __shared__ float Ds[PP*PP];
    __shared__ float dinv[64];
    int b = blockIdx.x, t = threadIdx.x;
    const float* Vb = g_Vfps + (size_t)b*PP*C1;
    for (int i = t; i < PP*64; i += 256) Vs[i] = Vb[i];
    __syncthreads();
    if (t < PP){
        float s = 0.f;
        for (int f = 0; f < 64; f++){ float v = Vs[t*64+f]; s = fmaf(v, v, s); }
        sqs[t] = s;
    }
    __syncthreads();
    for (int e = t; e < PP*PP; e += 256){
        int i = e / PP, j = e - i*PP;
        float dot = 0.f;
        for (int f = 0; f < 64; f++) dot = fmaf(Vs[i*64+f], Vs[j*64+f], dot);
        float dv = sqs[i] + sqs[j] - 2.0f*dot;
        Ds[e] = fmaxf(dv, 0.0f);
    }
    __syncthreads();
    if (t < PP){
        float s = 0.f;
        for (int j = 0; j < PP; j++) s += Ds[t*PP + j];
        dinv[t] = (s > 0.f) ? 1.0f/sqrtf(fmaxf(s, 1e-12f)) : 0.f;
    }
    __syncthreads();
    for (int e = t; e < PP*PP; e += 256){
        int i = e / PP, j = e - i*PP;
        float L = ((i == j) ? 1.0f : 0.0f) - Ds[e]*dinv[i]*dinv[j];
        g_Lfps[(size_t)b*PP*PP + e] = L;
    }
}

// ---------------- fused Chebyshev recursion (K=6), col-split x8, both graphs ----------------
__global__ __launch_bounds__(256) void k_cheb2(const float* __restrict__ Lreeb){
    __shared__ __align__(16) float Ls[64*64];
    __shared__ __align__(8) float Tc[64*8];
    int b = blockIdx.y, t = threadIdx.x, z = blockIdx.z;
    int NR = z ? PP : RR;
    const float* Lb = z ? (g_Lfps + (size_t)b*PP*PP) : (Lreeb + (size_t)b*RR*RR);
    const float* Vb = z ? (g_Vfps + (size_t)b*PP*C1) : (g_Vreeb + (size_t)b*RR*C1);
    float* xb = z ? (g_xkf + (size_t)b*PP*KF) : (g_xkr + (size_t)b*RR*KF);
    int c0 = blockIdx.x*8;
    for (int i = t; i < NR*NR; i += 256) Ls[i] = Lb[i];
    for (int i = t; i < NR*8; i += 256){
        int n = i >> 3, c = i & 7;
        float v = Vb[n*64 + c0 + c];
        Tc[i] = v;
        xb[n*KF + c0 + c] = v;
    }
    __syncthreads();
    int ty = t >> 2, tx = t & 3;   // ty: row 0..63, tx: col-pair 0..3 (2 cols each)
    int tyc = (ty < NR) ? ty : NR-1;
    float2 prev = *(const float2*)(Tc + tyc*8 + tx*2);
    float2 cur = make_float2(0,0);
    for (int m = 0; m < NR; m++){
        float a = Ls[tyc*NR + m];
        float2 b2 = *(const float2*)(Tc + m*8 + tx*2);
        cur.x = fmaf(a, b2.x, cur.x); cur.y = fmaf(a, b2.y, cur.y);
    }
    __syncthreads();
    if (ty < NR){
        *(float2*)(Tc + ty*8 + tx*2) = cur;
        *(float2*)(xb + ty*KF + 64 + c0 + tx*2) = cur;
    }
    __syncthreads();
    for (int kk = 2; kk < 6; kk++){
        float2 nxt = make_float2(0,0);
        for (int m = 0; m < NR; m++){
            float a = Ls[tyc*NR + m];
            float2 b2 = *(const float2*)(Tc + m*8 + tx*2);
            nxt.x = fmaf(a, b2.x, nxt.x); nxt.y = fmaf(a, b2.y, nxt.y);
        }
        nxt.x = 2.0f*nxt.x - prev.x; nxt.y = 2.0f*nxt.y - prev.y;
        prev = cur; cur = nxt;
        __syncthreads();
        if (ty < NR){
            *(float2*)(Tc + ty*8 + tx*2) = cur;
            *(float2*)(xb + ty*KF + kk*64 + c0 + tx*2) = cur;
        }
        __syncthreads();
    }
}

// ---------------- fused SGEMM (both): 32x64 tiles, C = relu(A @ W + bias) ----------------
__global__ __launch_bounds__(256) void k_gemm2(const float* __restrict__ Wr, const float* __restrict__ br,
                                               const float* __restrict__ Wf, const float* __restrict__ bf){
    __shared__ __align__(16) float As[32*16];
    __shared__ __align__(16) float Bs[16*64];
    int z = blockIdx.z;
    const float* A    = z ? g_xkf : g_xkr;
    const float* W    = z ? Wf : Wr;
    const float* bias = z ? bf : br;
    float* C          = z ? g_outf : g_outr;
    int M             = z ? BB*PP : BB*RR;
    int m0 = blockIdx.x*32, n0 = blockIdx.y*64;
    if (m0 >= M) return;
    int t = threadIdx.x, tx = t & 15, ty = t >> 4;
    float acc[2][4] = {};
    for (int k0 = 0; k0 < KF; k0 += 16){
        if (t < 128){
            int ar = t >> 2, ac = (t & 3)*4;
            int gr = m0 + ar;
            float4 av = (gr < M) ? *(const float4*)(A + (size_t)gr*KF + k0 + ac) : make_float4(0,0,0,0);
            *(float4*)(As + ar*16 + ac) = av;
        }
        int brr = t >> 4, bc = (t & 15)*4;
        float4 bv = *(const float4*)(W + (size_t)(k0 + brr)*256 + n0 + bc);
        *(float4*)(Bs + brr*64 + bc) = bv;
        __syncthreads();
        #pragma unroll
        for (int kk = 0; kk < 16; kk++){
            float a[2];
            #pragma unroll
            for (int u = 0; u < 2; u++) a[u] = As[(ty*2 + u)*16 + kk];
            float4 b4 = *(const float4*)(Bs + kk*64 + tx*4);
            #pragma unroll
            for (int u = 0; u < 2; u++){
                acc[u][0] = fmaf(a[u], b4.x, acc[u][0]);
                acc[u][1] = fmaf(a[u], b4.y, acc[u][1]);
                acc[u][2] = fmaf(a[u], b4.z, acc[u][2]);
                acc[u][3] = fmaf(a[u], b4.w, acc[u][3]);
            }
        }
        __syncthreads();
    }
    #pragma unroll
    for (int u = 0; u < 2; u++){
        int r = m0 + ty*2 + u;
        if (r < M){
            #pragma unroll
            for (int v = 0; v < 4; v++){
                int c = n0 + tx*4 + v;
                C[(size_t)r*256 + c] = fmaxf(acc[u][v] + bias[c], 0.f);
            }
        }
    }
}

// ---------------- fused Y = L @ X (both graphs, 32-col chunks) ----------------
__global__ __launch_bounds__(256) void k_Ymat2(const float* __restrict__ Lreeb){
    __shared__ __align__(16) float Ls[64*64];
    __shared__ __align__(16) float Xs[64*32];
    int b = blockIdx.y, t = threadIdx.x, z = blockIdx.z;
    int NR = z ? PP : RR;
    const float* Lb = z ? (g_Lfps + (size_t)b*PP*PP) : (Lreeb + (size_t)b*RR*RR);
    const float* Xb = z ? (g_outf + (size_t)b*PP*CH) : (g_outr + (size_t)b*RR*CH);
    float* Yb       = z ? (g_Yf   + (size_t)b*PP*CH) : (g_Yr   + (size_t)b*RR*CH);
    int c0 = blockIdx.x*32;
    for (int i = t; i < NR*NR; i += 256) Ls[i] = Lb[i];
    for (int i = t; i < NR*32; i += 256){ int n = i >> 5, c = i & 31; Xs[i] = Xb[n*256 + c0 + c]; }
    __syncthreads();
    int tx = t & 7, ty = t >> 3;   // tx: 8 col-quads (32 cols), ty: 32 row-pairs (64 rows)
    float acc[2][4] = {};
    for (int m = 0; m < NR; m++){
        float4 bv = *(const float4*)(Xs + m*32 + tx*4);
        float a[2];
        #pragma unroll
        for (int u = 0; u < 2; u++){ int n = u*32 + ty; if (n >= NR) n = NR-1; a[u] = Ls[n*NR + m]; }
        #pragma unroll
        for (int u = 0; u < 2; u++){
            acc[u][0] = fmaf(a[u], bv.x, acc[u][0]);
            acc[u][1] = fmaf(a[u], bv.y, acc[u][1]);
            acc[u][2] = fmaf(a[u], bv.z, acc[u][2]);
            acc[u][3] = fmaf(a[u], bv.w, acc[u][3]);
        }
    }
    #pragma unroll
    for (int u = 0; u < 2; u++){
        int n = u*32 + ty;
        if (n < NR){
            #pragma unroll
            for (int v = 0; v < 4; v++) Yb[(size_t)n*256 + c0 + tx*4 + v] = acc[u][v];
        }
    }
}

// ---------------- fused reg2/reg3: M' = X^T Y (64x64 tiles), sumsq partials ----------------
__global__ __launch_bounds__(256) void k_regM2(){
    __shared__ __align__(16) float sX[64*64];
    __shared__ __align__(16) float sY[64*64];
    int zz = blockIdx.z, t = threadIdx.x;
    int b = zz & 31, fps = zz >> 5;
    int NR = fps ? PP : RR;
    const float* Xb = fps ? (g_outf + (size_t)b*PP*CH) : (g_outr + (size_t)b*RR*CH);
    const float* Yb = fps ? (g_Yf   + (size_t)b*PP*CH) : (g_Yr   + (size_t)b*RR*CH);
    float* part     = fps ? g_p3 : g_p2;
    int f0 = blockIdx.x*64, g0 = blockIdx.y*64;
    for (int i = t; i < NR*64; i += 256){
        int n = i >> 6, j = i & 63;
        sX[i] = Xb[n*256 + f0 + j];
        sY[i] = Yb[n*256 + g0 + j];
    }
    __syncthreads();
    int tx = t & 15, ty = t >> 4;
    float acc[4][4] = {};
    for (int n = 0; n < NR; n++){
        float a[4];
        #pragma unroll
        for (int u = 0; u < 4; u++) a[u] = sX[n*64 + ty*4 + u];
        float4 b4 = *(const float4*)(sY + n*64 + tx*4);
        #pragma unroll
        for (int u = 0; u < 4; u++){
            acc[u][0] = fmaf(a[u], b4.x, acc[u][0]);
            acc[u][1] = fmaf(a[u], b4.y, acc[u][1]);
            acc[u][2] = fmaf(a[u], b4.z, acc[u][2]);
            acc[u][3] = fmaf(a[u], b4.w, acc[u][3]);
        }
    }
    float s = 0.f;
    #pragma unroll
    for (int u = 0; u < 4; u++)
        #pragma unroll
        for (int v = 0; v < 4; v++) s = fmaf(acc[u][v], acc[u][v], s);
    s = block_reduce_sum(s);
    if (t == 0) part[(b*4 + blockIdx.y)*4 + blockIdx.x] = s;
}

// ---------------- head: maxpool + fc1 + fc3 (+ regs vector on block 0) ----------------
__global__ __launch_bounds__(256) void k_head(const float* __restrict__ fc1w,
                                              const float* __restrict__ fc1b,
                                              const float* __restrict__ fc3w,
                                              const float* __restrict__ fc3b,
                                              float* __restrict__ out){
    __shared__ float feat[512];
    __shared__ float h[256];
    int b = blockIdx.x, t = threadIdx.x;
    float m = -3.4e38f;
    const float* orb = g_outr + (size_t)b*RR*CH;
    for (int n = 0; n < RR; n++) m = fmaxf(m, orb[n*CH + t]);
    feat[t] = m;
    m = -3.4e38f;
    const float* ofb = g_outf + (size_t)b*PP*CH;
    for (int n = 0; n < PP; n++) m = fmaxf(m, ofb[n*CH + t]);
    feat[256 + t] = m;
    __syncthreads();
    float acc = fc1b[t];
    #pragma unroll 4
    for (int i = 0; i < 512; i++) acc = fmaf(feat[i], fc1w[(size_t)i*256 + t], acc);
    h[t] = fmaxf(acc, 0.f);
    __syncthreads();
    if (t < 40){
        float a = fc3b[t];
        #pragma unroll 4
        for (int o = 0; o < 256; o++) a = fmaf(h[o], fc3w[o*40 + t], a);
        out[b*40 + t] = a;
    }
    if (b == 0){
        float a = 0.f;
        for (int i = t; i < 512; i += 256){ float v = fc1w[(size_t)i*256]; a = fmaf(v, v, a); }
        float r4 = block_reduce_sum(a);
        float c = 0.f;
        { float v = fc3w[t*40]; c = v*v; }
        float r6 = block_reduce_sum(c);
        float p = g_p1p[t];
        float r1 = block_reduce_sum(p);
        p = 0.f;
        for (int i = t; i < 512; i += 256) p += g_p2[i];
        float r2 = block_reduce_sum(p);
        p = 0.f;
        for (int i = t; i < 512; i += 256) p += g_p3[i];
        float r3 = block_reduce_sum(p);
        if (t == 0){
            out[1280] = r1; out[1281] = r2; out[1282] = r3; out[1283] = r4;
            float v1 = fc1b[0]; out[1284] = v1*v1;
            out[1285] = r6;
            float v3 = fc3b[0]; out[1286] = v3*v3;
        }
    }
}

// ---------------- launcher: single stream, no events ----------------
extern "C" void kernel_launch(void* const* d_in, const int* in_sizes, int n_in,
                              void* d_out, int out_size){
    (void)in_sizes; (void)n_in; (void)out_size;
    const float* x     = (const float*)d_in[0];
    const float* Lreeb = (const float*)d_in[2];
    const float* W1    = (const float*)d_in[3];
    const float* b1    = (const float*)d_in[4];
    const float* Wr    = (const float*)d_in[5];
    const float* br    = (const float*)d_in[6];
    const float* Wf    = (const float*)d_in[7];
    const float* bf    = (const float*)d_in[8];
    const float* fc1w  = (const float*)d_in[9];
    const float* fc1b  = (const float*)d_in[10];
    const float* fc3w  = (const float*)d_in[11];
    const float* fc3b  = (const float*)d_in[12];
    const int* sccs    = (const int*)d_in[13];
    const int* sccsf   = (const int*)d_in[14];
    float* out = (float*)d_out;

    int* nbr_p; cudaGetSymbolAddress((void**)&nbr_p, g_nbr);

    k_knn<<<dim3(32, BB), 256>>>(x, nbr_p);
    k_conv1<<<(BB*NN1)/128, 128>>>(x, W1, b1);
    k_Yknn<<<(BB*NN1*32)/256, 256>>>();
    k_reg1a<<<dim3(32, BB), 256>>>();
    k_reg1b<<<dim3(8, BB), 256>>>();
    k_vreeb<<<dim3(RR/4, BB), 256>>>(sccs);
    k_vfps<<<dim3(PP, BB), 256>>>(sccsf);
    k_Lfps<<<BB, 256>>>();
    k_cheb2<<<dim3(8, BB, 2), 256>>>(Lreeb);
    k_gemm2<<<dim3(64, 4, 2), 256>>>(Wr, br, Wf, bf);
    k_Ymat2<<<dim3(8, BB, 2), 256>>>(Lreeb);
    k_regM2<<<dim3(4, 4, 64), 256>>>();
    k_head<<<BB, 256>>>(fc1w, fc1b, fc3w, fc3b, out);
}

// round 10
// speedup vs baseline: 1.0366x; 1.0366x over previous
#include <cuda_runtime.h>
#include <cuda_bf16.h>
#include <cuda_fp16.h>
#include <math.h>

#define FULLM 0xffffffffu

// Problem constants (fixed by setup_inputs)
#define BB 32
#define NN1 1024
#define F0 7
#define KNN 30
#define C1 64
#define RR 64
#define SS 16
#define PP 55
#define CH 256
#define KF 384   // 6*64

// ---------------- scratch (static device globals; no runtime alloc) ----------------
__device__ int    g_nbr[BB*NN1*KNN];
__device__ float  g_t1p[BB*NN1*8];          // t1 padded to 8 floats
__device__ float  g_out[BB*NN1*C1];
__device__ __half g_outh[BB*NN1*C1];        // fp16 copy for byte-capped gathers
__device__ float  g_Y[BB*NN1*C1];
__device__ float  g_M1[BB*32*4096];
__device__ float  g_Vreeb[BB*RR*C1];
__device__ float  g_xkr[BB*RR*KF];
__device__ float  g_outr[BB*RR*CH];
__device__ float  g_Yr[BB*RR*CH];
__device__ float  g_Vfps[BB*PP*C1];
__device__ float  g_Lfps[BB*PP*PP];
__device__ float  g_xkf[BB*PP*KF];
__device__ float  g_outf[BB*PP*CH];
__device__ float  g_Yf[BB*PP*CH];
__device__ float  g_p1p[256];
__device__ float  g_p2[512];
__device__ float  g_p3[512];

// ---------------- helpers ----------------
__device__ __forceinline__ float block_reduce_sum(float v){
    __shared__ float sh[32];
    int lane = threadIdx.x & 31, w = threadIdx.x >> 5;
    #pragma unroll
    for (int o = 16; o; o >>= 1) v += __shfl_down_sync(FULLM, v, o);
    __syncthreads();
    if (lane == 0) sh[w] = v;
    __syncthreads();
    if (threadIdx.x == 0){
        float s = 0.f; int nw = blockDim.x >> 5;
        for (int i = 0; i < nw; i++) s += sh[i];
        return s;
    }
    return 0.f;
}

// ---------------- kNN: warp per row (4 rows/warp), threshold + survivor-compact ----------------
// Also emits t1 = L x (padded to 8 floats).
__global__ __launch_bounds__(256) void k_knn(const float* __restrict__ x, int* __restrict__ nbr){
    __shared__ float xT[F0*NN1];
    __shared__ float sq[NN1];
    __shared__ unsigned skey[8][256];
    __shared__ unsigned short ssid[8][256];
    int b = blockIdx.y;
    int tid = threadIdx.x;
    const float* xb = x + (size_t)b*NN1*F0;
    for (int n = tid; n < NN1; n += 256){
        float s = 0.f;
        #pragma unroll
        for (int f = 0; f < F0; f++){ float v = xb[n*F0+f]; xT[f*NN1+n] = v; s = fmaf(v, v, s); }
        sq[n] = s;
    }
    __syncthreads();
    int warp = tid >> 5, lane = tid & 31;
    unsigned* wk = skey[warp];
    unsigned short* wi = ssid[warp];
    for (int r = 0; r < 4; r++){
        int i = blockIdx.x*32 + warp*4 + r;
        float xi[F0];
        #pragma unroll
        for (int f = 0; f < F0; f++) xi[f] = xT[f*NN1+i];
        float sqi = sq[i];
        unsigned key[32];
        unsigned lmin = 0xFFFFFFFFu;
        #pragma unroll
        for (int t = 0; t < 32; t++){
            int j = t*32 + lane;
            float dot = 0.f;
            #pragma unroll
            for (int f = 0; f < F0; f++) dot = fmaf(xT[f*NN1+j], xi[f], dot);
            float dv = fmaxf(sqi + sq[j] - 2.0f*dot, 0.0f);
            unsigned kk = __float_as_uint(dv);   // monotone for d>=0
            key[t] = kk;
            lmin = min(lmin, kk);
        }
        unsigned thr = __reduce_max_sync(FULLM, lmin);
        unsigned cnt = 0;
        #pragma unroll
        for (int t = 0; t < 32; t++) cnt += (key[t] <= thr) ? 1u : 0u;
        unsigned S = __reduce_add_sync(FULLM, cnt);
        int base = ((b*NN1)+i)*KNN;
        float a_acc = 0.f;
        int myn = 0;
        if (S <= 256u){
            unsigned off = 0;
            #pragma unroll
            for (int t = 0; t < 32; t++){
                bool take = (key[t] <= thr);
                unsigned m = __ballot_sync(FULLM, take);
                if (take){
                    int pos = off + __popc(m & ((1u<<lane)-1u));
                    wk[pos] = key[t];
                    wi[pos] = (unsigned short)(t*32+lane);
                }
                off += __popc(m);
            }
            __syncwarp();
            unsigned sk[8]; unsigned sid[8];
            #pragma unroll
            for (int rr = 0; rr < 8; rr++){
                unsigned p = lane + rr*32;
                if (p < S){ sk[rr] = wk[p]; sid[rr] = wi[p]; }
                else      { sk[rr] = 0xFFFFFFFFu; sid[rr] = 0xFFFFu; }
            }
            unsigned bk = 0xFFFFFFFFu, bi = 0xFFFFFFFFu;
            #pragma unroll
            for (int rr = 0; rr < 8; rr++) if (sk[rr] < bk){ bk = sk[rr]; bi = sid[rr]; }
            for (int it = 0; it < KNN; it++){
                unsigned win = __reduce_min_sync(FULLM, bk);
                unsigned mask = __ballot_sync(FULLM, bk == win);
                unsigned widx;
                if (__popc(mask) == 1){
                    widx = __shfl_sync(FULLM, bi, __ffs(mask)-1);
                } else {
                    unsigned cand = (bk == win) ? bi : 0xFFFFFFFFu;
                    widx = __reduce_min_sync(FULLM, cand);
                }
                if (lane == it) myn = (int)widx;
                if (lane < F0) a_acc += xT[lane*NN1 + (int)widx];
                if (bk == win && bi == widx){
                    #pragma unroll
                    for (int rr = 0; rr < 8; rr++) if (sid[rr] == (unsigned short)widx) sk[rr] = 0xFFFFFFFFu;
                    bk = 0xFFFFFFFFu; bi = 0xFFFFFFFFu;
                    #pragma unroll
                    for (int rr = 0; rr < 8; rr++) if (sk[rr] < bk){ bk = sk[rr]; bi = sid[rr]; }
                }
            }
        } else {
            for (int it = 0; it < KNN; it++){
                unsigned bk = 0xFFFFFFFFu; int bt = 0;
                #pragma unroll
                for (int t = 0; t < 32; t++) if (key[t] < bk){ bk = key[t]; bt = t; }
                unsigned bi = (unsigned)(bt*32 + lane);
                #pragma unroll
                for (int o = 16; o; o >>= 1){
                    unsigned ok = __shfl_down_sync(FULLM, bk, o);
                    unsigned oi = __shfl_down_sync(FULLM, bi, o);
                    if (ok < bk || (ok == bk && oi < bi)){ bk = ok; bi = oi; }
                }
                unsigned widx = __shfl_sync(FULLM, bi, 0);
                if (lane == it) myn = (int)widx;
                if (lane < F0) a_acc += xT[lane*NN1 + (int)widx];
                if ((widx & 31u) == (unsigned)lane){
                    int slot = (int)(widx >> 5);
                    #pragma unroll
                    for (int t = 0; t < 32; t++) if (t == slot) key[t] = 0xFFFFFFFFu;
                }
            }
        }
        if (lane < KNN) nbr[base + lane] = myn;
        if (lane < 8){
            float v = (lane < F0) ? (xT[lane*NN1+i] - a_acc*(1.0f/30.0f)) : 0.0f;
            g_t1p[((size_t)(b*NN1)+i)*8 + lane] = v;
        }
        __syncwarp();
    }
}

// ---------------- conv1: out = relu([x|t1|t2] @ W1 + b1); also fp16 copy ----------------
__global__ __launch_bounds__(128) void k_conv1(const float* __restrict__ x,
                                               const float* __restrict__ W1,
                                               const float* __restrict__ b1){
    __shared__ float Ws[21*64];
    __shared__ float bs[64];
    for (int i = threadIdx.x; i < 21*64; i += blockDim.x) Ws[i] = W1[i];
    for (int i = threadIdx.x; i < 64; i += blockDim.x) bs[i] = b1[i];
    __syncthreads();
    int id = blockIdx.x*blockDim.x + threadIdx.x;
    int b = id >> 10, n = id & 1023;
    float in[21];
    const float* xr = x + (size_t)id*F0;
    #pragma unroll
    for (int f = 0; f < F0; f++) in[f] = xr[f];
    const float4* t1b4 = (const float4*)(g_t1p + (size_t)b*NN1*8);
    float4 own0 = t1b4[n*2], own1 = t1b4[n*2+1];
    in[7]=own0.x; in[8]=own0.y; in[9]=own0.z; in[10]=own0.w;
    in[11]=own1.x; in[12]=own1.y; in[13]=own1.z;
    float4 ac0 = make_float4(0,0,0,0), ac1 = make_float4(0,0,0,0);
    const int* nb = g_nbr + (size_t)id*KNN;
    #pragma unroll 2
    for (int s = 0; s < KNN; s++){
        int j = nb[s];
        float4 v0 = t1b4[j*2], v1 = t1b4[j*2+1];
        ac0.x += v0.x; ac0.y += v0.y; ac0.z += v0.z; ac0.w += v0.w;
        ac1.x += v1.x; ac1.y += v1.y; ac1.z += v1.z;
    }
    const float inv = 1.0f/30.0f;
    in[14] = 2.0f*(in[7]  - ac0.x*inv) - in[0];
    in[15] = 2.0f*(in[8]  - ac0.y*inv) - in[1];
    in[16] = 2.0f*(in[9]  - ac0.z*inv) - in[2];
    in[17] = 2.0f*(in[10] - ac0.w*inv) - in[3];
    in[18] = 2.0f*(in[11] - ac1.x*inv) - in[4];
    in[19] = 2.0f*(in[12] - ac1.y*inv) - in[5];
    in[20] = 2.0f*(in[13] - ac1.z*inv) - in[6];
    float o[64];
    #pragma unroll
    for (int c = 0; c < 64; c++) o[c] = bs[c];
    #pragma unroll
    for (int f = 0; f < 21; f++){
        float v = in[f];
        #pragma unroll
        for (int c = 0; c < 64; c++) o[c] = fmaf(v, Ws[f*64+c], o[c]);
    }
    float* orow = g_out + (size_t)id*C1;
    __half2* hrow = (__half2*)(g_outh + (size_t)id*C1);
    #pragma unroll
    for (int c = 0; c < 64; c += 2){
        float r0 = fmaxf(o[c], 0.f), r1 = fmaxf(o[c+1], 0.f);
        orow[c] = r0; orow[c+1] = r1;
        hrow[c>>1] = __floats2half2_rn(r0, r1);
    }
}

// ---------------- Y = L @ out (warp per node, fp16 gathers) ----------------
__global__ void k_Yknn(){
    int wid = (blockIdx.x*blockDim.x + threadIdx.x) >> 5;
    int lane = threadIdx.x & 31;
    if (wid >= BB*NN1) return;
    int b = wid >> 10;
    const __half2* ob = (const __half2*)(g_outh + (size_t)b*NN1*C1);
    const int* nb = g_nbr + (size_t)wid*KNN;
    float ax = 0.f, ay = 0.f;
    #pragma unroll 3
    for (int s = 0; s < KNN; s++){
        int j = nb[s];
        float2 f = __half22float2(ob[j*32 + lane]);
        ax += f.x; ay += f.y;
    }
    float2 orow = *(const float2*)(g_out + (size_t)wid*C1 + lane*2);
    float2 y;
    y.x = orow.x - ax*(1.0f/30.0f);
    y.y = orow.y - ay*(1.0f/30.0f);
    *(float2*)(g_Y + (size_t)wid*C1 + lane*2) = y;
}

// ---------------- reg1 phase A: partial M = out^T Y over one 32-row chunk ----------------
__global__ __launch_bounds__(256) void k_reg1a(){
    __shared__ __align__(16) float sA[32*64];
    __shared__ __align__(16) float sB[32*64];
    int c = blockIdx.x, b = blockIdx.y, t = threadIdx.x;
    const float* ob = g_out + (size_t)b*NN1*C1 + (size_t)c*32*64;
    const float* yb = g_Y   + (size_t)b*NN1*C1 + (size_t)c*32*64;
    for (int i = t; i < 2048; i += 256){ sA[i] = ob[i]; sB[i] = yb[i]; }
    __syncthreads();
    int tx = t & 15, ty = t >> 4;
    float acc[4][4] = {};
    #pragma unroll 4
    for (int n = 0; n < 32; n++){
        float a[4];
        #pragma unroll
        for (int u = 0; u < 4; u++) a[u] = sA[n*64 + ty*4 + u];
        float4 bv = *(const float4*)(sB + n*64 + tx*4);
        #pragma unroll
        for (int u = 0; u < 4; u++){
            acc[u][0] = fmaf(a[u], bv.x, acc[u][0]);
            acc[u][1] = fmaf(a[u], bv.y, acc[u][1]);
            acc[u][2] = fmaf(a[u], bv.z, acc[u][2]);
            acc[u][3] = fmaf(a[u], bv.w, acc[u][3]);
        }
    }
    float* mp = g_M1 + ((size_t)b*32 + c)*4096;
    #pragma unroll
    for (int u = 0; u < 4; u++)
        #pragma unroll
        for (int v = 0; v < 4; v++) mp[(ty*4+u)*64 + tx*4 + v] = acc[u][v];
}

// ---------------- reg1 phase B: parallel partial-sum + square ----------------
__global__ __launch_bounds__(256) void k_reg1b(){
    int piece = blockIdx.x, b = blockIdx.y, t = threadIdx.x;
    const float* mp = g_M1 + (size_t)b*32*4096;
    float s = 0.f;
    #pragma unroll
    for (int r = 0; r < 2; r++){
        int e = piece*512 + r*256 + t;
        float v = 0.f;
        #pragma unroll
        for (int c = 0; c < 32; c++) v += mp[c*4096 + e];
        s = fmaf(v, v, s);
    }
    s = block_reduce_sum(s);
    if (t == 0) g_p1p[b*8 + piece] = s;
}

// ---------------- segment max (reeb, fp32), 4 rows per 256-thread block ----------------
__global__ __launch_bounds__(256) void k_vreeb(const int* __restrict__ sccs){
    int r = blockIdx.x*4 + (threadIdx.x >> 6), b = blockIdx.y, f = threadIdx.x & 63;
    const int* sc = sccs + ((size_t)b*RR + r)*SS;
    const float* ob = g_out + (size_t)b*NN1*C1;
    float m = -3.4e38f;
    #pragma unroll 4
    for (int s = 0; s < SS; s++){ int idx = sc[s]; m = fmaxf(m, ob[idx*C1 + f]); }
    g_Vreeb[((size_t)b*RR + r)*C1 + f] = m;
}

// ---------------- segment max (fps): fp16 gathers, uint4 rows ----------------
__global__ __launch_bounds__(256) void k_vfps(const int* __restrict__ sf){
    __shared__ int sidx[1024];
    __shared__ float part[16][64];
    int p = blockIdx.x, b = blockIdx.y, t = threadIdx.x;
    const int4* si4 = (const int4*)(sf + ((size_t)b*PP + p)*NN1);
    ((int4*)sidx)[t] = si4[t];
    __syncthreads();
    const uint4* ob4 = (const uint4*)(g_outh + (size_t)b*NN1*C1);
    int grp = t >> 3, ln = t & 7;
    __half2 m0 = __float2half2_rn(0.f), m1 = m0, m2 = m0, m3 = m0;  // out >= 0 (relu)
    #pragma unroll 4
    for (int i = 0; i < 32; i++){
        int j = sidx[grp + i*32];
        uint4 v = ob4[j*8 + ln];
        m0 = __hmax2(m0, *(__half2*)&v.x);
        m1 = __hmax2(m1, *(__half2*)&v.y);
        m2 = __hmax2(m2, *(__half2*)&v.z);
        m3 = __hmax2(m3, *(__half2*)&v.w);
    }
    float2 f0 = __half22float2(m0), f1 = __half22float2(m1);
    float2 f2 = __half22float2(m2), f3 = __half22float2(m3);
    int slot = grp & 15;
    if (grp < 16){
        float* pr = &part[slot][ln*8];
        pr[0]=f0.x; pr[1]=f0.y; pr[2]=f1.x; pr[3]=f1.y;
        pr[4]=f2.x; pr[5]=f2.y; pr[6]=f3.x; pr[7]=f3.y;
    }
    __syncthreads();
    if (grp >= 16){
        float* pr = &part[slot][ln*8];
        pr[0]=fmaxf(pr[0],f0.x); pr[1]=fmaxf(pr[1],f0.y); pr[2]=fmaxf(pr[2],f1.x); pr[3]=fmaxf(pr[3],f1.y);
        pr[4]=fmaxf(pr[4],f2.x); pr[5]=fmaxf(pr[5],f2.y); pr[6]=fmaxf(pr[6],f3.x); pr[7]=fmaxf(pr[7],f3.y);
    }
    __syncthreads();
    if (t < 64){
        float mm = part[0][t];
        #pragma unroll
        for (int g = 1; g < 16; g++) mm = fmaxf(mm, part[g][t]);
        g_Vfps[((size_t)b*PP + p)*C1 + t] = mm;
    }
}

// ---------------- L_fps from pairwise distances of V_fps ----------------
__global__ __launch_bounds__(256) void k_Lfps(){
    __shared__ float Vs[PP*64];
    __shared__ float sqs[64];
    __shared__ float Ds[PP*PP];
    __shared__ float dinv[64];
    int b = blockIdx.x, t = threadIdx.x;
    const float* Vb = g_Vfps + (size_t)b*PP*C1;
    for (int i = t; i < PP*64; i += 256) Vs[i] = Vb[i];
    __syncthreads();
    if (t < PP){
        float s = 0.f;
        for (int f = 0; f < 64; f++){ float v = Vs[t*64+f]; s = fmaf(v, v, s); }
        sqs[t] = s;
    }
    __syncthreads();
    for (int e = t; e < PP*PP; e += 256){
        int i = e / PP, j = e - i*PP;
        float dot = 0.f;
        for (int f = 0; f < 64; f++) dot = fmaf(Vs[i*64+f], Vs[j*64+f], dot);
        float dv = sqs[i] + sqs[j] - 2.0f*dot;
        Ds[e] = fmaxf(dv, 0.0f);
    }
    __syncthreads();
    if (t < PP){
        float s = 0.f;
        for (int j = 0; j < PP; j++) s += Ds[t*PP + j];
        dinv[t] = (s > 0.f) ? 1.0f/sqrtf(fmaxf(s, 1e-12f)) : 0.f;
    }
    __syncthreads();
    for (int e = t; e < PP*PP; e += 256){
        int i = e / PP, j = e - i*PP;
        float L = ((i == j) ? 1.0f : 0.0f) - Ds[e]*dinv[i]*dinv[j];
        g_Lfps[(size_t)b*PP*PP + e] = L;
    }
}

// ---------------- fused Chebyshev recursion (K=6), col-split x4, both graphs ----------------
__global__ __launch_bounds__(256) void k_cheb2(const float* __restrict__ Lreeb){
    __shared__ __align__(16) float Ls[64*64];
    __shared__ __align__(16) float Tc[64*16];
    int b = blockIdx.y, t = threadIdx.x, z = blockIdx.z;
    int NR = z ? PP : RR;
    const float* Lb = z ? (g_Lfps + (size_t)b*PP*PP) : (Lreeb + (size_t)b*RR*RR);
    const float* Vb = z ? (g_Vfps + (size_t)b*PP*C1) : (g_Vreeb + (size_t)b*RR*C1);
    float* xb = z ? (g_xkf + (size_t)b*PP*KF) : (g_xkr + (size_t)b*RR*KF);
    int c0 = blockIdx.x*16;
    for (int i = t; i < NR*NR; i += 256) Ls[i] = Lb[i];
    for (int i = t; i < NR*16; i += 256){
        int n = i >> 4, c = i & 15;
        float v = Vb[n*64 + c0 + c];
        Tc[i] = v;
        xb[n*KF + c0 + c] = v;
    }
    __syncthreads();
    int ty = t >> 2, tx = t & 3;
    int tyc = (ty < NR) ? ty : NR-1;
    float4 prev = *(const float4*)(Tc + tyc*16 + tx*4);
    float4 cur = make_float4(0,0,0,0);
    for (int m = 0; m < NR; m++){
        float a = Ls[tyc*NR + m];
        float4 b4 = *(const float4*)(Tc + m*16 + tx*4);
        cur.x = fmaf(a, b4.x, cur.x); cur.y = fmaf(a, b4.y, cur.y);
        cur.z = fmaf(a, b4.z, cur.z); cur.w = fmaf(a, b4.w, cur.w);
    }
    __syncthreads();
    if (ty < NR){
        *(float4*)(Tc + ty*16 + tx*4) = cur;
        *(float4*)(xb + ty*KF + 64 + c0 + tx*4) = cur;
    }
    __syncthreads();
    for (int kk = 2; kk < 6; kk++){
        float4 nxt = make_float4(0,0,0,0);
        for (int m = 0; m < NR; m++){
            float a = Ls[tyc*NR + m];
            float4 b4 = *(const float4*)(Tc + m*16 + tx*4);
            nxt.x = fmaf(a, b4.x, nxt.x); nxt.y = fmaf(a, b4.y, nxt.y);
            nxt.z = fmaf(a, b4.z, nxt.z); nxt.w = fmaf(a, b4.w, nxt.w);
        }
        nxt.x = 2.0f*nxt.x - prev.x; nxt.y = 2.0f*nxt.y - prev.y;
        nxt.z = 2.0f*nxt.z - prev.z; nxt.w = 2.0f*nxt.w - prev.w;
        prev = cur; cur = nxt;
        __syncthreads();
        if (ty < NR){
            *(float4*)(Tc + ty*16 + tx*4) = cur;
            *(float4*)(xb + ty*KF + kk*64 + c0 + tx*4) = cur;
        }
        __syncthreads();
    }
}

// ---------------- fused SGEMM (both): C = relu(A[Mx384] @ W[384x256] + bias) ----------------
__global__ __launch_bounds__(256) void k_gemm2(const float* __restrict__ Wr, const float* __restrict__ br,
                                               const float* __restrict__ Wf, const float* __restrict__ bf){
    __shared__ __align__(16) float As[64*16];
    __shared__ __align__(16) float Bs[16*64];
    int z = blockIdx.z;
    const float* A    = z ? g_xkf : g_xkr;
    const float* W    = z ? Wf : Wr;
    const float* bias = z ? bf : br;
    float* C          = z ? g_outf : g_outr;
    int M             = z ? BB*PP : BB*RR;
    int m0 = blockIdx.x*64, n0 = blockIdx.y*64;
    if (m0 >= M) return;
    int t = threadIdx.x, tx = t & 15, ty = t >> 4;
    float acc[4][4] = {};
    for (int k0 = 0; k0 < KF; k0 += 16){
        int ar = t >> 2, ac = (t & 3)*4;
        int gr = m0 + ar;
        float4 av = (gr < M) ? *(const float4*)(A + (size_t)gr*KF + k0 + ac) : make_float4(0,0,0,0);
        *(float4*)(As + ar*16 + ac) = av;
        int brr = t >> 4, bc = (t & 15)*4;
        float4 bv = *(const float4*)(W + (size_t)(k0 + brr)*256 + n0 + bc);
        *(float4*)(Bs + brr*64 + bc) = bv;
        __syncthreads();
        #pragma unroll
        for (int kk = 0; kk < 16; kk++){
            float a[4];
            #pragma unroll
            for (int u = 0; u < 4; u++) a[u] = As[(ty*4 + u)*16 + kk];
            float4 b4 = *(const float4*)(Bs + kk*64 + tx*4);
            #pragma unroll
            for (int u = 0; u < 4; u++){
                acc[u][0] = fmaf(a[u], b4.x, acc[u][0]);
                acc[u][1] = fmaf(a[u], b4.y, acc[u][1]);
                acc[u][2] = fmaf(a[u], b4.z, acc[u][2]);
                acc[u][3] = fmaf(a[u], b4.w, acc[u][3]);
            }
        }
        __syncthreads();
    }
    #pragma unroll
    for (int u = 0; u < 4; u++){
        int r = m0 + ty*4 + u;
        if (r < M){
            #pragma unroll
            for (int v = 0; v < 4; v++){
                int c = n0 + tx*4 + v;
                C[(size_t)r*256 + c] = fmaxf(acc[u][v] + bias[c], 0.f);
            }
        }
    }
}

// ---------------- fused Y = L @ X (both graphs, 64-col chunks) ----------------
__global__ __launch_bounds__(256) void k_Ymat2(const float* __restrict__ Lreeb){
    __shared__ __align__(16) float Ls[64*64];
    __shared__ __align__(16) float Xs[64*64];
    int b = blockIdx.y, t = threadIdx.x, z = blockIdx.z;
    int NR = z ? PP : RR;
    const float* Lb = z ? (g_Lfps + (size_t)b*PP*PP) : (Lreeb + (size_t)b*RR*RR);
    const float* Xb = z ? (g_outf + (size_t)b*PP*CH) : (g_outr + (size_t)b*RR*CH);
    float* Yb       = z ? (g_Yf   + (size_t)b*PP*CH) : (g_Yr   + (size_t)b*RR*CH);
    int c0 = blockIdx.x*64;
    for (int i = t; i < NR*NR; i += 256) Ls[i] = Lb[i];
    for (int i = t; i < NR*64; i += 256){ int n = i >> 6, c = i & 63; Xs[i] = Xb[n*256 + c0 + c]; }
    __syncthreads();
    int tx = t & 15, ty = t >> 4;
    float acc[4][4] = {};
    for (int m = 0; m < NR; m++){
        float4 bv = *(const float4*)(Xs + m*64 + tx*4);
        float a[4];
        #pragma unroll
        for (int u = 0; u < 4; u++){ int n = ty*4 + u; if (n >= NR) n = NR-1; a[u] = Ls[n*NR + m]; }
        #pragma unroll
        for (int u = 0; u < 4; u++){
            acc[u][0] = fmaf(a[u], bv.x, acc[u][0]);
            acc[u][1] = fmaf(a[u], bv.y, acc[u][1]);
            acc[u][2] = fmaf(a[u], bv.z, acc[u][2]);
            acc[u][3] = fmaf(a[u], bv.w, acc[u][3]);
        }
    }
    #pragma unroll
    for (int u = 0; u < 4; u++){
        int n = ty*4 + u;
        if (n < NR){
            #pragma unroll
            for (int v = 0; v < 4; v++) Yb[(size_t)n*256 + c0 + tx*4 + v] = acc[u][v];
        }
    }
}

// ---------------- fused reg2/reg3: M' = X^T Y (64x64 tiles), sumsq partials ----------------
__global__ __launch_bounds__(256) void k_regM2(){
    __shared__ __align__(16) float sX[64*64];
    __shared__ __align__(16) float sY[64*64];
    int zz = blockIdx.z, t = threadIdx.x;
    int b = zz & 31, fps = zz >> 5;
    int NR = fps ? PP : RR;
    const float* Xb = fps ? (g_outf + (size_t)b*PP*CH) : (g_outr + (size_t)b*RR*CH);
    const float* Yb = fps ? (g_Yf   + (size_t)b*PP*CH) : (g_Yr   + (size_t)b*RR*CH);
    float* part     = fps ? g_p3 : g_p2;
    int f0 = blockIdx.x*64, g0 = blockIdx.y*64;
    for (int i = t; i < NR*64; i += 256){
        int n = i >> 6, j = i & 63;
        sX[i] = Xb[n*256 + f0 + j];
        sY[i] = Yb[n*256 + g0 + j];
    }
    __syncthreads();
    int tx = t & 15, ty = t >> 4;
    float acc[4][4] = {};
    for (int n = 0; n < NR; n++){
        float a[4];
        #pragma unroll
        for (int u = 0; u < 4; u++) a[u] = sX[n*64 + ty*4 + u];
        float4 b4 = *(const float4*)(sY + n*64 + tx*4);
        #pragma unroll
        for (int u = 0; u < 4; u++){
            acc[u][0] = fmaf(a[u], b4.x, acc[u][0]);
            acc[u][1] = fmaf(a[u], b4.y, acc[u][1]);
            acc[u][2] = fmaf(a[u], b4.z, acc[u][2]);
            acc[u][3] = fmaf(a[u], b4.w, acc[u][3]);
        }
    }
    float s = 0.f;
    #pragma unroll
    for (int u = 0; u < 4; u++)
        #pragma unroll
        for (int v = 0; v < 4; v++) s = fmaf(acc[u][v], acc[u][v], s);
    s = block_reduce_sum(s);
    if (t == 0) part[(b*4 + blockIdx.y)*4 + blockIdx.x] = s;
}

// ---------------- head: maxpool + fc1 + fc3 (+ regs vector on block 0) ----------------
__global__ __launch_bounds__(256) void k_head(const float* __restrict__ fc1w,
                                              const float* __restrict__ fc1b,
                                              const float* __restrict__ fc3w,
                                              const float* __restrict__ fc3b,
                                              float* __restrict__ out){
    __shared__ float feat[512];
    __shared__ float h[256];
    int b = blockIdx.x, t = threadIdx.x;
    float m = -3.4e38f;
    const float* orb = g_outr + (size_t)b*RR*CH;
    for (int n = 0; n < RR; n++) m = fmaxf(m, orb[n*CH + t]);
    feat[t] = m;
    m = -3.4e38f;
    const float* ofb = g_outf + (size_t)b*PP*CH;
    for (int n = 0; n < PP; n++) m = fmaxf(m, ofb[n*CH + t]);
    feat[256 + t] = m;
    __syncthreads();
    float acc = fc1b[t];
    #pragma unroll 4
    for (int i = 0; i < 512; i++) acc = fmaf(feat[i], fc1w[(size_t)i*256 + t], acc);
    h[t] = fmaxf(acc, 0.f);
    __syncthreads();
    if (t < 40){
        float a = fc3b[t];
        #pragma unroll 4
        for (int o = 0; o < 256; o++) a = fmaf(h[o], fc3w[o*40 + t], a);
        out[b*40 + t] = a;
    }
    if (b == 0){
        float a = 0.f;
        for (int i = t; i < 512; i += 256){ float v = fc1w[(size_t)i*256]; a = fmaf(v, v, a); }
        float r4 = block_reduce_sum(a);
        float c = 0.f;
        { float v = fc3w[t*40]; c = v*v; }
        float r6 = block_reduce_sum(c);
        float p = g_p1p[t];
        float r1 = block_reduce_sum(p);
        p = 0.f;
        for (int i = t; i < 512; i += 256) p += g_p2[i];
        float r2 = block_reduce_sum(p);
        p = 0.f;
        for (int i = t; i < 512; i += 256) p += g_p3[i];
        float r3 = block_reduce_sum(p);
        if (t == 0){
            out[1280] = r1; out[1281] = r2; out[1282] = r3; out[1283] = r4;
            float v1 = fc1b[0]; out[1284] = v1*v1;
            out[1285] = r6;
            float v3 = fc3b[0]; out[1286] = v3*v3;
        }
    }
}

// ---------------- launcher: single stream, no events ----------------
extern "C" void kernel_launch(void* const* d_in, const int* in_sizes, int n_in,
                              void* d_out, int out_size){
    (void)in_sizes; (void)n_in; (void)out_size;
    const float* x     = (const float*)d_in[0];
    const float* Lreeb = (const float*)d_in[2];
    const float* W1    = (const float*)d_in[3];
    const float* b1    = (const float*)d_in[4];
    const float* Wr    = (const float*)d_in[5];
    const float* br    = (const float*)d_in[6];
    const float* Wf    = (const float*)d_in[7];
    const float* bf    = (const float*)d_in[8];
    const float* fc1w  = (const float*)d_in[9];
    const float* fc1b  = (const float*)d_in[10];
    const float* fc3w  = (const float*)d_in[11];
    const float* fc3b  = (const float*)d_in[12];
    const int* sccs    = (const int*)d_in[13];
    const int* sccsf   = (const int*)d_in[14];
    float* out = (float*)d_out;

    int* nbr_p; cudaGetSymbolAddress((void**)&nbr_p, g_nbr);

    k_knn<<<dim3(32, BB), 256>>>(x, nbr_p);
    k_conv1<<<(BB*NN1)/128, 128>>>(x, W1, b1);
    k_Yknn<<<(BB*NN1*32)/256, 256>>>();
    k_reg1a<<<dim3(32, BB), 256>>>();
    k_reg1b<<<dim3(8, BB), 256>>>();
    k_vreeb<<<dim3(RR/4, BB), 256>>>(sccs);
    k_vfps<<<dim3(PP, BB), 256>>>(sccsf);
    k_Lfps<<<BB, 256>>>();
    k_cheb2<<<dim3(4, BB, 2), 256>>>(Lreeb);
    k_gemm2<<<dim3(32, 4, 2), 256>>>(Wr, br, Wf, bf);
    k_Ymat2<<<dim3(4, BB, 2), 256>>>(Lreeb);
    k_regM2<<<dim3(4, 4, 64), 256>>>();
    k_head<<<BB, 256>>>(fc1w, fc1b, fc3w, fc3b, out);
}

// round 11
// speedup vs baseline: 1.1213x; 1.0816x over previous
#include <cuda_runtime.h>
#include <cuda_bf16.h>
#include <cuda_fp16.h>
#include <math.h>

#define FULLM 0xffffffffu

// Problem constants (fixed by setup_inputs)
#define BB 32
#define NN1 1024
#define F0 7
#define KNN 30
#define C1 64
#define RR 64
#define SS 16
#define PP 55
#define CH 256
#define KF 384   // 6*64

// ---------------- scratch (static device globals; no runtime alloc) ----------------
__device__ int    g_nbr[BB*NN1*KNN];
__device__ float  g_t1p[BB*NN1*8];          // t1 padded to 8 floats
__device__ float  g_out[BB*NN1*C1];
__device__ __half g_outh[BB*NN1*C1];        // fp16 copy for byte-capped gathers
__device__ float  g_Y[BB*NN1*C1];
__device__ float  g_M1[BB*16*4096];
__device__ float  g_Vreeb[BB*RR*C1];
__device__ float  g_xkr[BB*RR*KF];
__device__ float  g_outr[BB*RR*CH];
__device__ float  g_Yr[BB*RR*CH];
__device__ float  g_Vfps[BB*PP*C1];
__device__ float  g_Lfps[BB*PP*PP];
__device__ float  g_xkf[BB*PP*KF];
__device__ float  g_outf[BB*PP*CH];
__device__ float  g_Yf[BB*PP*CH];
__device__ float  g_p1p[256];
__device__ float  g_p2[512];
__device__ float  g_p3[512];

// ---------------- helpers ----------------
__device__ __forceinline__ float block_reduce_sum(float v){
    __shared__ float sh[32];
    int lane = threadIdx.x & 31, w = threadIdx.x >> 5;
    #pragma unroll
    for (int o = 16; o; o >>= 1) v += __shfl_down_sync(FULLM, v, o);
    __syncthreads();
    if (lane == 0) sh[w] = v;
    __syncthreads();
    if (threadIdx.x == 0){
        float s = 0.f; int nw = blockDim.x >> 5;
        for (int i = 0; i < nw; i++) s += sh[i];
        return s;
    }
    return 0.f;
}

// ---------------- kNN: warp per row (4 rows/warp), threshold + survivor-compact ----------------
// Also emits t1 = L x (padded to 8 floats).
__global__ __launch_bounds__(256) void k_knn(const float* __restrict__ x, int* __restrict__ nbr){
    __shared__ float xT[F0*NN1];
    __shared__ float sq[NN1];
    __shared__ unsigned skey[8][256];
    __shared__ unsigned short ssid[8][256];
    int b = blockIdx.y;
    int tid = threadIdx.x;
    const float* xb = x + (size_t)b*NN1*F0;
    for (int n = tid; n < NN1; n += 256){
        float s = 0.f;
        #pragma unroll
        for (int f = 0; f < F0; f++){ float v = xb[n*F0+f]; xT[f*NN1+n] = v; s = fmaf(v, v, s); }
        sq[n] = s;
    }
    __syncthreads();
    int warp = tid >> 5, lane = tid & 31;
    unsigned* wk = skey[warp];
    unsigned short* wi = ssid[warp];
    for (int r = 0; r < 4; r++){
        int i = blockIdx.x*32 + warp*4 + r;
        float xi[F0];
        #pragma unroll
        for (int f = 0; f < F0; f++) xi[f] = xT[f*NN1+i];
        float sqi = sq[i];
        unsigned key[32];
        unsigned lmin = 0xFFFFFFFFu;
        #pragma unroll
        for (int t = 0; t < 32; t++){
            int j = t*32 + lane;
            float dot = 0.f;
            #pragma unroll
            for (int f = 0; f < F0; f++) dot = fmaf(xT[f*NN1+j], xi[f], dot);
            float dv = fmaxf(sqi + sq[j] - 2.0f*dot, 0.0f);
            unsigned kk = __float_as_uint(dv);   // monotone for d>=0
            key[t] = kk;
            lmin = min(lmin, kk);
        }
        unsigned thr = __reduce_max_sync(FULLM, lmin);
        unsigned cnt = 0;
        #pragma unroll
        for (int t = 0; t < 32; t++) cnt += (key[t] <= thr) ? 1u : 0u;
        unsigned S = __reduce_add_sync(FULLM, cnt);
        int base = ((b*NN1)+i)*KNN;
        float a_acc = 0.f;
        int myn = 0;
        if (S <= 256u){
            unsigned off = 0;
            #pragma unroll
            for (int t = 0; t < 32; t++){
                bool take = (key[t] <= thr);
                unsigned m = __ballot_sync(FULLM, take);
                if (take){
                    int pos = off + __popc(m & ((1u<<lane)-1u));
                    wk[pos] = key[t];
                    wi[pos] = (unsigned short)(t*32+lane);
                }
                off += __popc(m);
            }
            __syncwarp();
            unsigned sk[8]; unsigned sid[8];
            #pragma unroll
            for (int rr = 0; rr < 8; rr++){
                unsigned p = lane + rr*32;
                if (p < S){ sk[rr] = wk[p]; sid[rr] = wi[p]; }
                else      { sk[rr] = 0xFFFFFFFFu; sid[rr] = 0xFFFFu; }
            }
            unsigned bk = 0xFFFFFFFFu, bi = 0xFFFFFFFFu;
            #pragma unroll
            for (int rr = 0; rr < 8; rr++) if (sk[rr] < bk){ bk = sk[rr]; bi = sid[rr]; }
            for (int it = 0; it < KNN; it++){
                unsigned win = __reduce_min_sync(FULLM, bk);
                unsigned mask = __ballot_sync(FULLM, bk == win);
                unsigned widx;
                if (__popc(mask) == 1){
                    widx = __shfl_sync(FULLM, bi, __ffs(mask)-1);
                } else {
                    unsigned cand = (bk == win) ? bi : 0xFFFFFFFFu;
                    widx = __reduce_min_sync(FULLM, cand);
                }
                if (lane == it) myn = (int)widx;
                if (lane < F0) a_acc += xT[lane*NN1 + (int)widx];
                if (bk == win && bi == widx){
                    #pragma unroll
                    for (int rr = 0; rr < 8; rr++) if (sid[rr] == (unsigned short)widx) sk[rr] = 0xFFFFFFFFu;
                    bk = 0xFFFFFFFFu; bi = 0xFFFFFFFFu;
                    #pragma unroll
                    for (int rr = 0; rr < 8; rr++) if (sk[rr] < bk){ bk = sk[rr]; bi = sid[rr]; }
                }
            }
        } else {
            for (int it = 0; it < KNN; it++){
                unsigned bk = 0xFFFFFFFFu; int bt = 0;
                #pragma unroll
                for (int t = 0; t < 32; t++) if (key[t] < bk){ bk = key[t]; bt = t; }
                unsigned bi = (unsigned)(bt*32 + lane);
                #pragma unroll
                for (int o = 16; o; o >>= 1){
                    unsigned ok = __shfl_down_sync(FULLM, bk, o);
                    unsigned oi = __shfl_down_sync(FULLM, bi, o);
                    if (ok < bk || (ok == bk && oi < bi)){ bk = ok; bi = oi; }
                }
                unsigned widx = __shfl_sync(FULLM, bi, 0);
                if (lane == it) myn = (int)widx;
                if (lane < F0) a_acc += xT[lane*NN1 + (int)widx];
                if ((widx & 31u) == (unsigned)lane){
                    int slot = (int)(widx >> 5);
                    #pragma unroll
                    for (int t = 0; t < 32; t++) if (t == slot) key[t] = 0xFFFFFFFFu;
                }
            }
        }
        if (lane < KNN) nbr[base + lane] = myn;
        if (lane < 8){
            float v = (lane < F0) ? (xT[lane*NN1+i] - a_acc*(1.0f/30.0f)) : 0.0f;
            g_t1p[((size_t)(b*NN1)+i)*8 + lane] = v;
        }
        __syncwarp();
    }
}

// ---------------- conv1: out = relu([x|t1|t2] @ W1 + b1); also fp16 copy ----------------
__global__ __launch_bounds__(128) void k_conv1(const float* __restrict__ x,
                                               const float* __restrict__ W1,
                                               const float* __restrict__ b1){
    __shared__ float Ws[21*64];
    __shared__ float bs[64];
    for (int i = threadIdx.x; i < 21*64; i += blockDim.x) Ws[i] = W1[i];
    for (int i = threadIdx.x; i < 64; i += blockDim.x) bs[i] = b1[i];
    __syncthreads();
    int id = blockIdx.x*blockDim.x + threadIdx.x;
    int b = id >> 10, n = id & 1023;
    float in[21];
    const float* xr = x + (size_t)id*F0;
    #pragma unroll
    for (int f = 0; f < F0; f++) in[f] = xr[f];
    const float4* t1b4 = (const float4*)(g_t1p + (size_t)b*NN1*8);
    float4 own0 = t1b4[n*2], own1 = t1b4[n*2+1];
    in[7]=own0.x; in[8]=own0.y; in[9]=own0.z; in[10]=own0.w;
    in[11]=own1.x; in[12]=own1.y; in[13]=own1.z;
    float4 ac0 = make_float4(0,0,0,0), ac1 = make_float4(0,0,0,0);
    const int* nb = g_nbr + (size_t)id*KNN;
    #pragma unroll 2
    for (int s = 0; s < KNN; s++){
        int j = nb[s];
        float4 v0 = t1b4[j*2], v1 = t1b4[j*2+1];
        ac0.x += v0.x; ac0.y += v0.y; ac0.z += v0.z; ac0.w += v0.w;
        ac1.x += v1.x; ac1.y += v1.y; ac1.z += v1.z;
    }
    const float inv = 1.0f/30.0f;
    in[14] = 2.0f*(in[7]  - ac0.x*inv) - in[0];
    in[15] = 2.0f*(in[8]  - ac0.y*inv) - in[1];
    in[16] = 2.0f*(in[9]  - ac0.z*inv) - in[2];
    in[17] = 2.0f*(in[10] - ac0.w*inv) - in[3];
    in[18] = 2.0f*(in[11] - ac1.x*inv) - in[4];
    in[19] = 2.0f*(in[12] - ac1.y*inv) - in[5];
    in[20] = 2.0f*(in[13] - ac1.z*inv) - in[6];
    float o[64];
    #pragma unroll
    for (int c = 0; c < 64; c++) o[c] = bs[c];
    #pragma unroll
    for (int f = 0; f < 21; f++){
        float v = in[f];
        #pragma unroll
        for (int c = 0; c < 64; c++) o[c] = fmaf(v, Ws[f*64+c], o[c]);
    }
    float* orow = g_out + (size_t)id*C1;
    __half2* hrow = (__half2*)(g_outh + (size_t)id*C1);
    #pragma unroll
    for (int c = 0; c < 64; c += 2){
        float r0 = fmaxf(o[c], 0.f), r1 = fmaxf(o[c+1], 0.f);
        orow[c] = r0; orow[c+1] = r1;
        hrow[c>>1] = __floats2half2_rn(r0, r1);
    }
}

// ---------------- Y = L @ out (warp per node, fp16 gathers) ----------------
__global__ void k_Yknn(){
    int wid = (blockIdx.x*blockDim.x + threadIdx.x) >> 5;
    int lane = threadIdx.x & 31;
    if (wid >= BB*NN1) return;
    int b = wid >> 10;
    const __half2* ob = (const __half2*)(g_outh + (size_t)b*NN1*C1);
    const int* nb = g_nbr + (size_t)wid*KNN;
    float ax = 0.f, ay = 0.f;
    #pragma unroll 3
    for (int s = 0; s < KNN; s++){
        int j = nb[s];
        float2 f = __half22float2(ob[j*32 + lane]);
        ax += f.x; ay += f.y;
    }
    float2 orow = *(const float2*)(g_out + (size_t)wid*C1 + lane*2);
    float2 y;
    y.x = orow.x - ax*(1.0f/30.0f);
    y.y = orow.y - ay*(1.0f/30.0f);
    *(float2*)(g_Y + (size_t)wid*C1 + lane*2) = y;
}

// ---------------- reg1 phase A: partial M = out^T Y over one 64-row chunk ----------------
__global__ __launch_bounds__(256) void k_reg1a(){
    __shared__ __align__(16) float sA[64*64];
    __shared__ __align__(16) float sB[64*64];
    int c = blockIdx.x, b = blockIdx.y, t = threadIdx.x;
    const float* ob = g_out + (size_t)b*NN1*C1 + (size_t)c*64*64;
    const float* yb = g_Y   + (size_t)b*NN1*C1 + (size_t)c*64*64;
    for (int i = t; i < 4096; i += 256){ sA[i] = ob[i]; sB[i] = yb[i]; }
    __syncthreads();
    int tx = t & 15, ty = t >> 4;
    float acc[4][4] = {};
    #pragma unroll 4
    for (int n = 0; n < 64; n++){
        float a[4];
        #pragma unroll
        for (int u = 0; u < 4; u++) a[u] = sA[n*64 + ty*4 + u];
        float4 bv = *(const float4*)(sB + n*64 + tx*4);
        #pragma unroll
        for (int u = 0; u < 4; u++){
            acc[u][0] = fmaf(a[u], bv.x, acc[u][0]);
            acc[u][1] = fmaf(a[u], bv.y, acc[u][1]);
            acc[u][2] = fmaf(a[u], bv.z, acc[u][2]);
            acc[u][3] = fmaf(a[u], bv.w, acc[u][3]);
        }
    }
    float* mp = g_M1 + ((size_t)b*16 + c)*4096;
    #pragma unroll
    for (int u = 0; u < 4; u++)
        #pragma unroll
        for (int v = 0; v < 4; v++) mp[(ty*4+u)*64 + tx*4 + v] = acc[u][v];
}

// ---------------- reg1 phase B: parallel partial-sum + square (256 blocks) ----------------
__global__ __launch_bounds__(256) void k_reg1b(){
    int piece = blockIdx.x, b = blockIdx.y, t = threadIdx.x;
    const float* mp = g_M1 + (size_t)b*16*4096;
    float s = 0.f;
    #pragma unroll
    for (int r = 0; r < 2; r++){
        int e = piece*512 + r*256 + t;
        float v = 0.f;
        #pragma unroll
        for (int c = 0; c < 16; c++) v += mp[c*4096 + e];
        s = fmaf(v, v, s);
    }
    s = block_reduce_sum(s);
    if (t == 0) g_p1p[b*8 + piece] = s;
}

// ---------------- fused segment max: x<55 -> fps pooling, x>=55 -> 4 reeb rows ----------------
__global__ __launch_bounds__(256) void k_vpool(const int* __restrict__ sf, const int* __restrict__ sccs){
    int b = blockIdx.y, t = threadIdx.x;
    if (blockIdx.x >= PP){
        // reeb branch: rows 4*(blockIdx.x-55) .. +3
        int r = (blockIdx.x - PP)*4 + (t >> 6), f = t & 63;
        const int* sc = sccs + ((size_t)b*RR + r)*SS;
        const float* ob = g_out + (size_t)b*NN1*C1;
        float m = -3.4e38f;
        #pragma unroll 4
        for (int s = 0; s < SS; s++){ int idx = sc[s]; m = fmaxf(m, ob[idx*C1 + f]); }
        g_Vreeb[((size_t)b*RR + r)*C1 + f] = m;
        return;
    }
    // fps branch
    __shared__ int sidx[1024];
    __shared__ float part[16][64];
    int p = blockIdx.x;
    const int4* si4 = (const int4*)(sf + ((size_t)b*PP + p)*NN1);
    ((int4*)sidx)[t] = si4[t];
    __syncthreads();
    const uint4* ob4 = (const uint4*)(g_outh + (size_t)b*NN1*C1);
    int grp = t >> 3, ln = t & 7;
    __half2 m0 = __float2half2_rn(0.f), m1 = m0, m2 = m0, m3 = m0;  // out >= 0 (relu)
    #pragma unroll 4
    for (int i = 0; i < 32; i++){
        int j = sidx[grp + i*32];
        uint4 v = ob4[j*8 + ln];
        m0 = __hmax2(m0, *(__half2*)&v.x);
        m1 = __hmax2(m1, *(__half2*)&v.y);
        m2 = __hmax2(m2, *(__half2*)&v.z);
        m3 = __hmax2(m3, *(__half2*)&v.w);
    }
    float2 f0 = __half22float2(m0), f1 = __half22float2(m1);
    float2 f2 = __half22float2(m2), f3 = __half22float2(m3);
    int slot = grp & 15;
    if (grp < 16){
        float* pr = &part[slot][ln*8];
        pr[0]=f0.x; pr[1]=f0.y; pr[2]=f1.x; pr[3]=f1.y;
        pr[4]=f2.x; pr[5]=f2.y; pr[6]=f3.x; pr[7]=f3.y;
    }
    __syncthreads();
    if (grp >= 16){
        float* pr = &part[slot][ln*8];
        pr[0]=fmaxf(pr[0],f0.x); pr[1]=fmaxf(pr[1],f0.y); pr[2]=fmaxf(pr[2],f1.x); pr[3]=fmaxf(pr[3],f1.y);
        pr[4]=fmaxf(pr[4],f2.x); pr[5]=fmaxf(pr[5],f2.y); pr[6]=fmaxf(pr[6],f3.x); pr[7]=fmaxf(pr[7],f3.y);
    }
    __syncthreads();
    if (t < 64){
        float mm = part[0][t];
        #pragma unroll
        for (int g = 1; g < 16; g++) mm = fmaxf(mm, part[g][t]);
        g_Vfps[((size_t)b*PP + p)*C1 + t] = mm;
    }
}

// ---------------- L_fps from pairwise distances of V_fps ----------------
__global__ __launch_bounds__(256) void k_Lfps(){
    __shared__ float Vs[PP*64];
    __shared__ float sqs[64];
    __shared__ float Ds[PP*PP];
    __shared__ float dinv[64];
    int b = blockIdx.x, t = threadIdx.x;
    const float* Vb = g_Vfps + (size_t)b*PP*C1;
    for (int i = t; i < PP*64; i += 256) Vs[i] = Vb[i];
    __syncthreads();
    if (t < PP){
        float s = 0.f;
        for (int f = 0; f < 64; f++){ float v = Vs[t*64+f]; s = fmaf(v, v, s); }
        sqs[t] = s;
    }
    __syncthreads();
    for (int e = t; e < PP*PP; e += 256){
        int i = e / PP, j = e - i*PP;
        float dot = 0.f;
        for (int f = 0; f < 64; f++) dot = fmaf(Vs[i*64+f], Vs[j*64+f], dot);
        float dv = sqs[i] + sqs[j] - 2.0f*dot;
        Ds[e] = fmaxf(dv, 0.0f);
    }
    __syncthreads();
    if (t < PP){
        float s = 0.f;
        for (int j = 0; j < PP; j++) s += Ds[t*PP + j];
        dinv[t] = (s > 0.f) ? 1.0f/sqrtf(fmaxf(s, 1e-12f)) : 0.f;
    }
    __syncthreads();
    for (int e = t; e < PP*PP; e += 256){
        int i = e / PP, j = e - i*PP;
        float L = ((i == j) ? 1.0f : 0.0f) - Ds[e]*dinv[i]*dinv[j];
        g_Lfps[(size_t)b*PP*PP + e] = L;
    }
}

// ---------------- fused Chebyshev recursion (K=6), col-split x4, both graphs ----------------
__global__ __launch_bounds__(256) void k_cheb2(const float* __restrict__ Lreeb){
    __shared__ __align__(16) float Ls[64*64];
    __shared__ __align__(16) float Tc[64*16];
    int b = blockIdx.y, t = threadIdx.x, z = blockIdx.z;
    int NR = z ? PP : RR;
    const float* Lb = z ? (g_Lfps + (size_t)b*PP*PP) : (Lreeb + (size_t)b*RR*RR);
    const float* Vb = z ? (g_Vfps + (size_t)b*PP*C1) : (g_Vreeb + (size_t)b*RR*C1);
    float* xb = z ? (g_xkf + (size_t)b*PP*KF) : (g_xkr + (size_t)b*RR*KF);
    int c0 = blockIdx.x*16;
    for (int i = t; i < NR*NR; i += 256) Ls[i] = Lb[i];
    for (int i = t; i < NR*16; i += 256){
        int n = i >> 4, c = i & 15;
        float v = Vb[n*64 + c0 + c];
        Tc[i] = v;
        xb[n*KF + c0 + c] = v;
    }
    __syncthreads();
    int ty = t >> 2, tx = t & 3;
    int tyc = (ty < NR) ? ty : NR-1;
    float4 prev = *(const float4*)(Tc + tyc*16 + tx*4);
    float4 cur = make_float4(0,0,0,0);
    for (int m = 0; m < NR; m++){
        float a = Ls[tyc*NR + m];
        float4 b4 = *(const float4*)(Tc + m*16 + tx*4);
        cur.x = fmaf(a, b4.x, cur.x); cur.y = fmaf(a, b4.y, cur.y);
        cur.z = fmaf(a, b4.z, cur.z); cur.w = fmaf(a, b4.w, cur.w);
    }
    __syncthreads();
    if (ty < NR){
        *(float4*)(Tc + ty*16 + tx*4) = cur;
        *(float4*)(xb + ty*KF + 64 + c0 + tx*4) = cur;
    }
    __syncthreads();
    for (int kk = 2; kk < 6; kk++){
        float4 nxt = make_float4(0,0,0,0);
        for (int m = 0; m < NR; m++){
            float a = Ls[tyc*NR + m];
            float4 b4 = *(const float4*)(Tc + m*16 + tx*4);
            nxt.x = fmaf(a, b4.x, nxt.x); nxt.y = fmaf(a, b4.y, nxt.y);
            nxt.z = fmaf(a, b4.z, nxt.z); nxt.w = fmaf(a, b4.w, nxt.w);
        }
        nxt.x = 2.0f*nxt.x - prev.x; nxt.y = 2.0f*nxt.y - prev.y;
        nxt.z = 2.0f*nxt.z - prev.z; nxt.w = 2.0f*nxt.w - prev.w;
        prev = cur; cur = nxt;
        __syncthreads();
        if (ty < NR){
            *(float4*)(Tc + ty*16 + tx*4) = cur;
            *(float4*)(xb + ty*KF + kk*64 + c0 + tx*4) = cur;
        }
        __syncthreads();
    }
}

// ---------------- fused SGEMM (both): C = relu(A[Mx384] @ W[384x256] + bias) ----------------
__global__ __launch_bounds__(256) void k_gemm2(const float* __restrict__ Wr, const float* __restrict__ br,
                                               const float* __restrict__ Wf, const float* __restrict__ bf){
    __shared__ __align__(16) float As[64*16];
    __shared__ __align__(16) float Bs[16*64];
    int z = blockIdx.z;
    const float* A    = z ? g_xkf : g_xkr;
    const float* W    = z ? Wf : Wr;
    const float* bias = z ? bf : br;
    float* C          = z ? g_outf : g_outr;
    int M             = z ? BB*PP : BB*RR;
    int m0 = blockIdx.x*64, n0 = blockIdx.y*64;
    if (m0 >= M) return;
    int t = threadIdx.x, tx = t & 15, ty = t >> 4;
    float acc[4][4] = {};
    for (int k0 = 0; k0 < KF; k0 += 16){
        int ar = t >> 2, ac = (t & 3)*4;
        int gr = m0 + ar;
        float4 av = (gr < M) ? *(const float4*)(A + (size_t)gr*KF + k0 + ac) : make_float4(0,0,0,0);
        *(float4*)(As + ar*16 + ac) = av;
        int brr = t >> 4, bc = (t & 15)*4;
        float4 bv = *(const float4*)(W + (size_t)(k0 + brr)*256 + n0 + bc);
        *(float4*)(Bs + brr*64 + bc) = bv;
        __syncthreads();
        #pragma unroll
        for (int kk = 0; kk < 16; kk++){
            float a[4];
            #pragma unroll
            for (int u = 0; u < 4; u++) a[u] = As[(ty*4 + u)*16 + kk];
            float4 b4 = *(const float4*)(Bs + kk*64 + tx*4);
            #pragma unroll
            for (int u = 0; u < 4; u++){
                acc[u][0] = fmaf(a[u], b4.x, acc[u][0]);
                acc[u][1] = fmaf(a[u], b4.y, acc[u][1]);
                acc[u][2] = fmaf(a[u], b4.z, acc[u][2]);
                acc[u][3] = fmaf(a[u], b4.w, acc[u][3]);
            }
        }
        __syncthreads();
    }
    #pragma unroll
    for (int u = 0; u < 4; u++){
        int r = m0 + ty*4 + u;
        if (r < M){
            #pragma unroll
            for (int v = 0; v < 4; v++){
                int c = n0 + tx*4 + v;
                C[(size_t)r*256 + c] = fmaxf(acc[u][v] + bias[c], 0.f);
            }
        }
    }
}

// ---------------- fused Y = L @ X (both graphs, 64-col chunks) ----------------
__global__ __launch_bounds__(256) void k_Ymat2(const float* __restrict__ Lreeb){
    __shared__ __align__(16) float Ls[64*64];
    __shared__ __align__(16) float Xs[64*64];
    int b = blockIdx.y, t = threadIdx.x, z = blockIdx.z;
    int NR = z ? PP : RR;
    const float* Lb = z ? (g_Lfps + (size_t)b*PP*PP) : (Lreeb + (size_t)b*RR*RR);
    const float* Xb = z ? (g_outf + (size_t)b*PP*CH) : (g_outr + (size_t)b*RR*CH);
    float* Yb       = z ? (g_Yf   + (size_t)b*PP*CH) : (g_Yr   + (size_t)b*RR*CH);
    int c0 = blockIdx.x*64;
    for (int i = t; i < NR*NR; i += 256) Ls[i] = Lb[i];
    for (int i = t; i < NR*64; i += 256){ int n = i >> 6, c = i & 63; Xs[i] = Xb[n*256 + c0 + c]; }
    __syncthreads();
    int tx = t & 15, ty = t >> 4;
    float acc[4][4] = {};
    for (int m = 0; m < NR; m++){
        float4 bv = *(const float4*)(Xs + m*64 + tx*4);
        float a[4];
        #pragma unroll
        for (int u = 0; u < 4; u++){ int n = ty*4 + u; if (n >= NR) n = NR-1; a[u] = Ls[n*NR + m]; }
        #pragma unroll
        for (int u = 0; u < 4; u++){
            acc[u][0] = fmaf(a[u], bv.x, acc[u][0]);
            acc[u][1] = fmaf(a[u], bv.y, acc[u][1]);
            acc[u][2] = fmaf(a[u], bv.z, acc[u][2]);
            acc[u][3] = fmaf(a[u], bv.w, acc[u][3]);
        }
    }
    #pragma unroll
    for (int u = 0; u < 4; u++){
        int n = ty*4 + u;
        if (n < NR){
            #pragma unroll
            for (int v = 0; v < 4; v++) Yb[(size_t)n*256 + c0 + tx*4 + v] = acc[u][v];
        }
    }
}

// ---------------- fused reg2/reg3: M' = X^T Y (64x64 tiles), sumsq partials ----------------
__global__ __launch_bounds__(256) void k_regM2(){
    __shared__ __align__(16) float sX[64*64];
    __shared__ __align__(16) float sY[64*64];
    int zz = blockIdx.z, t = threadIdx.x;
    int b = zz & 31, fps = zz >> 5;
    int NR = fps ? PP : RR;
    const float* Xb = fps ? (g_outf + (size_t)b*PP*CH) : (g_outr + (size_t)b*RR*CH);
    const float* Yb = fps ? (g_Yf   + (size_t)b*PP*CH) : (g_Yr   + (size_t)b*RR*CH);
    float* part     = fps ? g_p3 : g_p2;
    int f0 = blockIdx.x*64, g0 = blockIdx.y*64;
    for (int i = t; i < NR*64; i += 256){
        int n = i >> 6, j = i & 63;
        sX[i] = Xb[n*256 + f0 + j];
        sY[i] = Yb[n*256 + g0 + j];
    }
    __syncthreads();
    int tx = t & 15, ty = t >> 4;
    float acc[4][4] = {};
    for (int n = 0; n < NR; n++){
        float a[4];
        #pragma unroll
        for (int u = 0; u < 4; u++) a[u] = sX[n*64 + ty*4 + u];
        float4 b4 = *(const float4*)(sY + n*64 + tx*4);
        #pragma unroll
        for (int u = 0; u < 4; u++){
            acc[u][0] = fmaf(a[u], b4.x, acc[u][0]);
            acc[u][1] = fmaf(a[u], b4.y, acc[u][1]);
            acc[u][2] = fmaf(a[u], b4.z, acc[u][2]);
            acc[u][3] = fmaf(a[u], b4.w, acc[u][3]);
        }
    }
    float s = 0.f;
    #pragma unroll
    for (int u = 0; u < 4; u++)
        #pragma unroll
        for (int v = 0; v < 4; v++) s = fmaf(acc[u][v], acc[u][v], s);
    s = block_reduce_sum(s);
    if (t == 0) part[(b*4 + blockIdx.y)*4 + blockIdx.x] = s;
}

// ---------------- head: maxpool + fc1 + fc3 (+ regs vector on block 0) ----------------
__global__ __launch_bounds__(256) void k_head(const float* __restrict__ fc1w,
                                              const float* __restrict__ fc1b,
                                              const float* __restrict__ fc3w,
                                              const float* __restrict__ fc3b,
                                              float* __restrict__ out){
    __shared__ float feat[512];
    __shared__ float h[256];
    int b = blockIdx.x, t = threadIdx.x;
    float m = -3.4e38f;
    const float* orb = g_outr + (size_t)b*RR*CH;
    for (int n = 0; n < RR; n++) m = fmaxf(m, orb[n*CH + t]);
    feat[t] = m;
    m = -3.4e38f;
    const float* ofb = g_outf + (size_t)b*PP*CH;
    for (int n = 0; n < PP; n++) m = fmaxf(m, ofb[n*CH + t]);
    feat[256 + t] = m;
    __syncthreads();
    float acc = fc1b[t];
    #pragma unroll 4
    for (int i = 0; i < 512; i++) acc = fmaf(feat[i], fc1w[(size_t)i*256 + t], acc);
    h[t] = fmaxf(acc, 0.f);
    __syncthreads();
    if (t < 40){
        float a = fc3b[t];
        #pragma unroll 4
        for (int o = 0; o < 256; o++) a = fmaf(h[o], fc3w[o*40 + t], a);
        out[b*40 + t] = a;
    }
    if (b == 0){
        float a = 0.f;
        for (int i = t; i < 512; i += 256){ float v = fc1w[(size_t)i*256]; a = fmaf(v, v, a); }
        float r4 = block_reduce_sum(a);
        float c = 0.f;
        { float v = fc3w[t*40]; c = v*v; }
        float r6 = block_reduce_sum(c);
        float p = g_p1p[t];
        float r1 = block_reduce_sum(p);
        p = 0.f;
        for (int i = t; i < 512; i += 256) p += g_p2[i];
        float r2 = block_reduce_sum(p);
        p = 0.f;
        for (int i = t; i < 512; i += 256) p += g_p3[i];
        float r3 = block_reduce_sum(p);
        if (t == 0){
            out[1280] = r1; out[1281] = r2; out[1282] = r3; out[1283] = r4;
            float v1 = fc1b[0]; out[1284] = v1*v1;
            out[1285] = r6;
            float v3 = fc3b[0]; out[1286] = v3*v3;
        }
    }
}

// ---------------- launcher: single stream, no events ----------------
extern "C" void kernel_launch(void* const* d_in, const int* in_sizes, int n_in,
                              void* d_out, int out_size){
    (void)in_sizes; (void)n_in; (void)out_size;
    const float* x     = (const float*)d_in[0];
    const float* Lreeb = (const float*)d_in[2];
    const float* W1    = (const float*)d_in[3];
    const float* b1    = (const float*)d_in[4];
    const float* Wr    = (const float*)d_in[5];
    const float* br    = (const float*)d_in[6];
    const float* Wf    = (const float*)d_in[7];
    const float* bf    = (const float*)d_in[8];
    const float* fc1w  = (const float*)d_in[9];
    const float* fc1b  = (const float*)d_in[10];
    const float* fc3w  = (const float*)d_in[11];
    const float* fc3b  = (const float*)d_in[12];
    const int* sccs    = (const int*)d_in[13];
    const int* sccsf   = (const int*)d_in[14];
    float* out = (float*)d_out;

    int* nbr_p; cudaGetSymbolAddress((void**)&nbr_p, g_nbr);

    k_knn<<<dim3(32, BB), 256>>>(x, nbr_p);
    k_conv1<<<(BB*NN1)/128, 128>>>(x, W1, b1);
    k_Yknn<<<(BB*NN1*32)/256, 256>>>();
    k_reg1a<<<dim3(16, BB), 256>>>();
    k_reg1b<<<dim3(8, BB), 256>>>();
    k_vpool<<<dim3(PP + RR/4, BB), 256>>>(sccsf, sccs);
    k_Lfps<<<BB, 256>>>();
    k_cheb2<<<dim3(4, BB, 2), 256>>>(Lreeb);
    k_gemm2<<<dim3(32, 4, 2), 256>>>(Wr, br, Wf, bf);
    k_Ymat2<<<dim3(4, BB, 2), 256>>>(Lreeb);
    k_regM2<<<dim3(4, 4, 64), 256>>>();
    k_head<<<BB, 256>>>(fc1w, fc1b, fc3w, fc3b, out);
}

// round 12
// speedup vs baseline: 1.3017x; 1.1609x over previous
#include <cuda_runtime.h>
#include <cuda_bf16.h>
#include <cuda_fp16.h>
#include <math.h>

#define FULLM 0xffffffffu

// Problem constants (fixed by setup_inputs)
#define BB 32
#define NN1 1024
#define F0 7
#define KNN 30
#define C1 64
#define RR 64
#define SS 16
#define PP 55
#define CH 256
#define KF 384   // 6*64

// ---------------- scratch (static device globals; no runtime alloc) ----------------
__device__ int    g_nbr[BB*NN1*KNN];
__device__ float  g_t1p[BB*NN1*8];          // t1 padded to 8 floats
__device__ float  g_out[BB*NN1*C1];
__device__ __half g_outh[BB*NN1*C1];        // fp16 copy for byte-capped gathers
__device__ float  g_Y[BB*NN1*C1];
__device__ float  g_M1[BB*16*4096];
__device__ float  g_Vreeb[BB*RR*C1];
__device__ float  g_xkr[BB*RR*KF];
__device__ float  g_outr[BB*RR*CH];
__device__ float  g_Yr[BB*RR*CH];
__device__ float  g_Vfps[BB*PP*C1];
__device__ float  g_Lfps[BB*PP*PP];
__device__ float  g_xkf[BB*PP*KF];
__device__ float  g_outf[BB*PP*CH];
__device__ float  g_Yf[BB*PP*CH];
__device__ float  g_p1p[256];
__device__ float  g_p2[512];
__device__ float  g_p3[512];

// ---------------- helpers ----------------
__device__ __forceinline__ float block_reduce_sum(float v){
    __shared__ float sh[32];
    int lane = threadIdx.x & 31, w = threadIdx.x >> 5;
    #pragma unroll
    for (int o = 16; o; o >>= 1) v += __shfl_down_sync(FULLM, v, o);
    __syncthreads();
    if (lane == 0) sh[w] = v;
    __syncthreads();
    if (threadIdx.x == 0){
        float s = 0.f; int nw = blockDim.x >> 5;
        for (int i = 0; i < nw; i++) s += sh[i];
        return s;
    }
    return 0.f;
}

// ---------------- kNN: warp per row (4 rows/warp), threshold + packed-key selection ----------------
// Packed survivor value = (key & 0xFFFFFC00) | idx  -> one REDUX per extract-min,
// key-then-lowest-index lexicographic order. Also emits t1 = L x (padded to 8 floats).
__global__ __launch_bounds__(256) void k_knn(const float* __restrict__ x, int* __restrict__ nbr){
    __shared__ float xT[F0*NN1];
    __shared__ float sq[NN1];
    __shared__ unsigned skey[8][256];
    int b = blockIdx.y;
    int tid = threadIdx.x;
    const float* xb = x + (size_t)b*NN1*F0;
    for (int n = tid; n < NN1; n += 256){
        float s = 0.f;
        #pragma unroll
        for (int f = 0; f < F0; f++){ float v = xb[n*F0+f]; xT[f*NN1+n] = v; s = fmaf(v, v, s); }
        sq[n] = s;
    }
    __syncthreads();
    int warp = tid >> 5, lane = tid & 31;
    unsigned* wk = skey[warp];
    for (int r = 0; r < 4; r++){
        int i = blockIdx.x*32 + warp*4 + r;
        float xi[F0];
        #pragma unroll
        for (int f = 0; f < F0; f++) xi[f] = xT[f*NN1+i];
        float sqi = sq[i];
        unsigned key[32];
        unsigned lmin = 0xFFFFFFFFu;
        #pragma unroll
        for (int t = 0; t < 32; t++){
            int j = t*32 + lane;
            float dot = 0.f;
            #pragma unroll
            for (int f = 0; f < F0; f++) dot = fmaf(xT[f*NN1+j], xi[f], dot);
            float dv = fmaxf(sqi + sq[j] - 2.0f*dot, 0.0f);
            unsigned kk = __float_as_uint(dv);   // monotone for d>=0
            key[t] = kk;
            lmin = min(lmin, kk);
        }
        unsigned thr = __reduce_max_sync(FULLM, lmin);
        unsigned cnt = 0;
        #pragma unroll
        for (int t = 0; t < 32; t++) cnt += (key[t] <= thr) ? 1u : 0u;
        unsigned S = __reduce_add_sync(FULLM, cnt);
        int base = ((b*NN1)+i)*KNN;
        float a_acc = 0.f;
        int myn = 0;
        if (S <= 256u){
            unsigned off = 0;
            #pragma unroll
            for (int t = 0; t < 32; t++){
                bool take = (key[t] <= thr);
                unsigned m = __ballot_sync(FULLM, take);
                if (take){
                    int pos = off + __popc(m & ((1u<<lane)-1u));
                    wk[pos] = (key[t] & 0xFFFFFC00u) | (unsigned)(t*32+lane);
                }
                off += __popc(m);
            }
            __syncwarp();
            unsigned sv[8];
            #pragma unroll
            for (int rr = 0; rr < 8; rr++){
                unsigned p = lane + rr*32;
                sv[rr] = (p < S) ? wk[p] : 0xFFFFFFFFu;
            }
            unsigned pk = 0xFFFFFFFFu;
            #pragma unroll
            for (int rr = 0; rr < 8; rr++) pk = min(pk, sv[rr]);
            for (int it = 0; it < KNN; it++){
                unsigned win = __reduce_min_sync(FULLM, pk);
                unsigned widx = win & 1023u;
                if (lane == it) myn = (int)widx;
                if (lane < F0) a_acc += xT[lane*NN1 + (int)widx];
                if (pk == win){
                    #pragma unroll
                    for (int rr = 0; rr < 8; rr++) if (sv[rr] == win) sv[rr] = 0xFFFFFFFFu;
                    pk = 0xFFFFFFFFu;
                    #pragma unroll
                    for (int rr = 0; rr < 8; rr++) pk = min(pk, sv[rr]);
                }
            }
        } else {
            // rare exact fallback over full keys (packed per-slot on the fly)
            for (int it = 0; it < KNN; it++){
                unsigned bk = 0xFFFFFFFFu; int bt = 0;
                #pragma unroll
                for (int t = 0; t < 32; t++) if (key[t] < bk){ bk = key[t]; bt = t; }
                unsigned bi = (unsigned)(bt*32 + lane);
                #pragma unroll
                for (int o = 16; o; o >>= 1){
                    unsigned ok = __shfl_down_sync(FULLM, bk, o);
                    unsigned oi = __shfl_down_sync(FULLM, bi, o);
                    if (ok < bk || (ok == bk && oi < bi)){ bk = ok; bi = oi; }
                }
                unsigned widx = __shfl_sync(FULLM, bi, 0);
                if (lane == it) myn = (int)widx;
                if (lane < F0) a_acc += xT[lane*NN1 + (int)widx];
                if ((widx & 31u) == (unsigned)lane){
                    int slot = (int)(widx >> 5);
                    #pragma unroll
                    for (int t = 0; t < 32; t++) if (t == slot) key[t] = 0xFFFFFFFFu;
                }
            }
        }
        if (lane < KNN) nbr[base + lane] = myn;
        if (lane < 8){
            float v = (lane < F0) ? (xT[lane*NN1+i] - a_acc*(1.0f/30.0f)) : 0.0f;
            g_t1p[((size_t)(b*NN1)+i)*8 + lane] = v;
        }
        __syncwarp();
    }
}

// ---------------- conv1: out = relu([x|t1|t2] @ W1 + b1); also fp16 copy ----------------
__global__ __launch_bounds__(128) void k_conv1(const float* __restrict__ x,
                                               const float* __restrict__ W1,
                                               const float* __restrict__ b1){
    __shared__ float Ws[21*64];
    __shared__ float bs[64];
    for (int i = threadIdx.x; i < 21*64; i += blockDim.x) Ws[i] = W1[i];
    for (int i = threadIdx.x; i < 64; i += blockDim.x) bs[i] = b1[i];
    __syncthreads();
    int id = blockIdx.x*blockDim.x + threadIdx.x;
    int b = id >> 10, n = id & 1023;
    float in[21];
    const float* xr = x + (size_t)id*F0;
    #pragma unroll
    for (int f = 0; f < F0; f++) in[f] = xr[f];
    const float4* t1b4 = (const float4*)(g_t1p + (size_t)b*NN1*8);
    float4 own0 = t1b4[n*2], own1 = t1b4[n*2+1];
    in[7]=own0.x; in[8]=own0.y; in[9]=own0.z; in[10]=own0.w;
    in[11]=own1.x; in[12]=own1.y; in[13]=own1.z;
    float4 ac0 = make_float4(0,0,0,0), ac1 = make_float4(0,0,0,0);
    const int* nb = g_nbr + (size_t)id*KNN;
    #pragma unroll 2
    for (int s = 0; s < KNN; s++){
        int j = nb[s];
        float4 v0 = t1b4[j*2], v1 = t1b4[j*2+1];
        ac0.x += v0.x; ac0.y += v0.y; ac0.z += v0.z; ac0.w += v0.w;
        ac1.x += v1.x; ac1.y += v1.y; ac1.z += v1.z;
    }
    const float inv = 1.0f/30.0f;
    in[14] = 2.0f*(in[7]  - ac0.x*inv) - in[0];
    in[15] = 2.0f*(in[8]  - ac0.y*inv) - in[1];
    in[16] = 2.0f*(in[9]  - ac0.z*inv) - in[2];
    in[17] = 2.0f*(in[10] - ac0.w*inv) - in[3];
    in[18] = 2.0f*(in[11] - ac1.x*inv) - in[4];
    in[19] = 2.0f*(in[12] - ac1.y*inv) - in[5];
    in[20] = 2.0f*(in[13] - ac1.z*inv) - in[6];
    float o[64];
    #pragma unroll
    for (int c = 0; c < 64; c++) o[c] = bs[c];
    #pragma unroll
    for (int f = 0; f < 21; f++){
        float v = in[f];
        #pragma unroll
        for (int c = 0; c < 64; c++) o[c] = fmaf(v, Ws[f*64+c], o[c]);
    }
    float* orow = g_out + (size_t)id*C1;
    __half2* hrow = (__half2*)(g_outh + (size_t)id*C1);
    #pragma unroll
    for (int c = 0; c < 64; c += 2){
        float r0 = fmaxf(o[c], 0.f), r1 = fmaxf(o[c+1], 0.f);
        orow[c] = r0; orow[c+1] = r1;
        hrow[c>>1] = __floats2half2_rn(r0, r1);
    }
}

// ---------------- Y = L @ out (warp per node, fp16 gathers) ----------------
__global__ void k_Yknn(){
    int wid = (blockIdx.x*blockDim.x + threadIdx.x) >> 5;
    int lane = threadIdx.x & 31;
    if (wid >= BB*NN1) return;
    int b = wid >> 10;
    const __half2* ob = (const __half2*)(g_outh + (size_t)b*NN1*C1);
    const int* nb = g_nbr + (size_t)wid*KNN;
    float ax = 0.f, ay = 0.f;
    #pragma unroll 3
    for (int s = 0; s < KNN; s++){
        int j = nb[s];
        float2 f = __half22float2(ob[j*32 + lane]);
        ax += f.x; ay += f.y;
    }
    float2 orow = *(const float2*)(g_out + (size_t)wid*C1 + lane*2);
    float2 y;
    y.x = orow.x - ax*(1.0f/30.0f);
    y.y = orow.y - ay*(1.0f/30.0f);
    *(float2*)(g_Y + (size_t)wid*C1 + lane*2) = y;
}

// ---------------- reg1 phase A: partial M = out^T Y over one 64-row chunk ----------------
__global__ __launch_bounds__(256) void k_reg1a(){
    __shared__ __align__(16) float sA[64*64];
    __shared__ __align__(16) float sB[64*64];
    int c = blockIdx.x, b = blockIdx.y, t = threadIdx.x;
    const float* ob = g_out + (size_t)b*NN1*C1 + (size_t)c*64*64;
    const float* yb = g_Y   + (size_t)b*NN1*C1 + (size_t)c*64*64;
    for (int i = t; i < 4096; i += 256){ sA[i] = ob[i]; sB[i] = yb[i]; }
    __syncthreads();
    int tx = t & 15, ty = t >> 4;
    float acc[4][4] = {};
    #pragma unroll 4
    for (int n = 0; n < 64; n++){
        float a[4];
        #pragma unroll
        for (int u = 0; u < 4; u++) a[u] = sA[n*64 + ty*4 + u];
        float4 bv = *(const float4*)(sB + n*64 + tx*4);
        #pragma unroll
        for (int u = 0; u < 4; u++){
            acc[u][0] = fmaf(a[u], bv.x, acc[u][0]);
            acc[u][1] = fmaf(a[u], bv.y, acc[u][1]);
            acc[u][2] = fmaf(a[u], bv.z, acc[u][2]);
            acc[u][3] = fmaf(a[u], bv.w, acc[u][3]);
        }
    }
    float* mp = g_M1 + ((size_t)b*16 + c)*4096;
    #pragma unroll
    for (int u = 0; u < 4; u++)
        #pragma unroll
        for (int v = 0; v < 4; v++) mp[(ty*4+u)*64 + tx*4 + v] = acc[u][v];
}

// ---------------- reg1 phase B: parallel partial-sum + square (256 blocks) ----------------
__global__ __launch_bounds__(256) void k_reg1b(){
    int piece = blockIdx.x, b = blockIdx.y, t = threadIdx.x;
    const float* mp = g_M1 + (size_t)b*16*4096;
    float s = 0.f;
    #pragma unroll
    for (int r = 0; r < 2; r++){
        int e = piece*512 + r*256 + t;
        float v = 0.f;
        #pragma unroll
        for (int c = 0; c < 16; c++) v += mp[c*4096 + e];
        s = fmaf(v, v, s);
    }
    s = block_reduce_sum(s);
    if (t == 0) g_p1p[b*8 + piece] = s;
}

// ---------------- fused segment max: x<55 -> fps pooling, x>=55 -> 4 reeb rows ----------------
__global__ __launch_bounds__(256) void k_vpool(const int* __restrict__ sf, const int* __restrict__ sccs){
    int b = blockIdx.y, t = threadIdx.x;
    if (blockIdx.x >= PP){
        int r = (blockIdx.x - PP)*4 + (t >> 6), f = t & 63;
        const int* sc = sccs + ((size_t)b*RR + r)*SS;
        const float* ob = g_out + (size_t)b*NN1*C1;
        float m = -3.4e38f;
        #pragma unroll 4
        for (int s = 0; s < SS; s++){ int idx = sc[s]; m = fmaxf(m, ob[idx*C1 + f]); }
        g_Vreeb[((size_t)b*RR + r)*C1 + f] = m;
        return;
    }
    __shared__ int sidx[1024];
    __shared__ float part[16][64];
    int p = blockIdx.x;
    const int4* si4 = (const int4*)(sf + ((size_t)b*PP + p)*NN1);
    ((int4*)sidx)[t] = si4[t];
    __syncthreads();
    const uint4* ob4 = (const uint4*)(g_outh + (size_t)b*NN1*C1);
    int grp = t >> 3, ln = t & 7;
    __half2 m0 = __float2half2_rn(0.f), m1 = m0, m2 = m0, m3 = m0;  // out >= 0 (relu)
    #pragma unroll 4
    for (int i = 0; i < 32; i++){
        int j = sidx[grp + i*32];
        uint4 v = ob4[j*8 + ln];
        m0 = __hmax2(m0, *(__half2*)&v.x);
        m1 = __hmax2(m1, *(__half2*)&v.y);
        m2 = __hmax2(m2, *(__half2*)&v.z);
        m3 = __hmax2(m3, *(__half2*)&v.w);
    }
    float2 f0 = __half22float2(m0), f1 = __half22float2(m1);
    float2 f2 = __half22float2(m2), f3 = __half22float2(m3);
    int slot = grp & 15;
    if (grp < 16){
        float* pr = &part[slot][ln*8];
        pr[0]=f0.x; pr[1]=f0.y; pr[2]=f1.x; pr[3]=f1.y;
        pr[4]=f2.x; pr[5]=f2.y; pr[6]=f3.x; pr[7]=f3.y;
    }
    __syncthreads();
    if (grp >= 16){
        float* pr = &part[slot][ln*8];
        pr[0]=fmaxf(pr[0],f0.x); pr[1]=fmaxf(pr[1],f0.y); pr[2]=fmaxf(pr[2],f1.x); pr[3]=fmaxf(pr[3],f1.y);
        pr[4]=fmaxf(pr[4],f2.x); pr[5]=fmaxf(pr[5],f2.y); pr[6]=fmaxf(pr[6],f3.x); pr[7]=fmaxf(pr[7],f3.y);
    }
    __syncthreads();
    if (t < 64){
        float mm = part[0][t];
        #pragma unroll
        for (int g = 1; g < 16; g++) mm = fmaxf(mm, part[g][t]);
        g_Vfps[((size_t)b*PP + p)*C1 + t] = mm;
    }
}

// ---------------- L_fps from pairwise distances of V_fps ----------------
__global__ __launch_bounds__(256) void k_Lfps(){
    __shared__ float Vs[PP*64];
    __shared__ float sqs[64];
    __shared__ float Ds[PP*PP];
    __shared__ float dinv[64];
    int b = blockIdx.x, t = threadIdx.x;
    const float* Vb = g_Vfps + (size_t)b*PP*C1;
    for (int i = t; i < PP*64; i += 256) Vs[i] = Vb[i];
    __syncthreads();
    if (t < PP){
        float s = 0.f;
        for (int f = 0; f < 64; f++){ float v = Vs[t*64+f]; s = fmaf(v, v, s); }
        sqs[t] = s;
    }
    __syncthreads();
    for (int e = t; e < PP*PP; e += 256){
        int i = e / PP, j = e - i*PP;
        float dot = 0.f;
        for (int f = 0; f < 64; f++) dot = fmaf(Vs[i*64+f], Vs[j*64+f], dot);
        float dv = sqs[i] + sqs[j] - 2.0f*dot;
        Ds[e] = fmaxf(dv, 0.0f);
    }
    __syncthreads();
    if (t < PP){
        float s = 0.f;
        for (int j = 0; j < PP; j++) s += Ds[t*PP + j];
        dinv[t] = (s > 0.f) ? 1.0f/sqrtf(fmaxf(s, 1e-12f)) : 0.f;
    }
    __syncthreads();
    for (int e = t; e < PP*PP; e += 256){
        int i = e / PP, j = e - i*PP;
        float L = ((i == j) ? 1.0f : 0.0f) - Ds[e]*dinv[i]*dinv[j];
        g_Lfps[(size_t)b*PP*PP + e] = L;
    }
}

// ---------------- fused Chebyshev recursion (K=6), col-split x4, both graphs ----------------
__global__ __launch_bounds__(256) void k_cheb2(const float* __restrict__ Lreeb){
    __shared__ __align__(16) float Ls[64*64];
    __shared__ __align__(16) float Tc[64*16];
    int b = blockIdx.y, t = threadIdx.x, z = blockIdx.z;
    int NR = z ? PP : RR;
    const float* Lb = z ? (g_Lfps + (size_t)b*PP*PP) : (Lreeb + (size_t)b*RR*RR);
    const float* Vb = z ? (g_Vfps + (size_t)b*PP*C1) : (g_Vreeb + (size_t)b*RR*C1);
    float* xb = z ? (g_xkf + (size_t)b*PP*KF) : (g_xkr + (size_t)b*RR*KF);
    int c0 = blockIdx.x*16;
    for (int i = t; i < NR*NR; i += 256) Ls[i] = Lb[i];
    for (int i = t; i < NR*16; i += 256){
        int n = i >> 4, c = i & 15;
        float v = Vb[n*64 + c0 + c];
        Tc[i] = v;
        xb[n*KF + c0 + c] = v;
    }
    __syncthreads();
    int ty = t >> 2, tx = t & 3;
    int tyc = (ty < NR) ? ty : NR-1;
    float4 prev = *(const float4*)(Tc + tyc*16 + tx*4);
    float4 cur = make_float4(0,0,0,0);
    for (int m = 0; m < NR; m++){
        float a = Ls[tyc*NR + m];
        float4 b4 = *(const float4*)(Tc + m*16 + tx*4);
        cur.x = fmaf(a, b4.x, cur.x); cur.y = fmaf(a, b4.y, cur.y);
        cur.z = fmaf(a, b4.z, cur.z); cur.w = fmaf(a, b4.w, cur.w);
    }
    __syncthreads();
    if (ty < NR){
        *(float4*)(Tc + ty*16 + tx*4) = cur;
        *(float4*)(xb + ty*KF + 64 + c0 + tx*4) = cur;
    }
    __syncthreads();
    for (int kk = 2; kk < 6; kk++){
        float4 nxt = make_float4(0,0,0,0);
        for (int m = 0; m < NR; m++){
            float a = Ls[tyc*NR + m];
            float4 b4 = *(const float4*)(Tc + m*16 + tx*4);
            nxt.x = fmaf(a, b4.x, nxt.x); nxt.y = fmaf(a, b4.y, nxt.y);
            nxt.z = fmaf(a, b4.z, nxt.z); nxt.w = fmaf(a, b4.w, nxt.w);
        }
        nxt.x = 2.0f*nxt.x - prev.x; nxt.y = 2.0f*nxt.y - prev.y;
        nxt.z = 2.0f*nxt.z - prev.z; nxt.w = 2.0f*nxt.w - prev.w;
        prev = cur; cur = nxt;
        __syncthreads();
        if (ty < NR){
            *(float4*)(Tc + ty*16 + tx*4) = cur;
            *(float4*)(xb + ty*KF + kk*64 + c0 + tx*4) = cur;
        }
        __syncthreads();
    }
}

// ---------------- fused SGEMM (both): C = relu(A[Mx384] @ W[384x256] + bias) ----------------
__global__ __launch_bounds__(256) void k_gemm2(const float* __restrict__ Wr, const float* __restrict__ br,
                                               const float* __restrict__ Wf, const float* __restrict__ bf){
    __shared__ __align__(16) float As[64*16];
    __shared__ __align__(16) float Bs[16*64];
    int z = blockIdx.z;
    const float* A    = z ? g_xkf : g_xkr;
    const float* W    = z ? Wf : Wr;
    const float* bias = z ? bf : br;
    float* C          = z ? g_outf : g_outr;
    int M             = z ? BB*PP : BB*RR;
    int m0 = blockIdx.x*64, n0 = blockIdx.y*64;
    if (m0 >= M) return;
    int t = threadIdx.x, tx = t & 15, ty = t >> 4;
    float acc[4][4] = {};
    for (int k0 = 0; k0 < KF; k0 += 16){
        int ar = t >> 2, ac = (t & 3)*4;
        int gr = m0 + ar;
        float4 av = (gr < M) ? *(const float4*)(A + (size_t)gr*KF + k0 + ac) : make_float4(0,0,0,0);
        *(float4*)(As + ar*16 + ac) = av;
        int brr = t >> 4, bc = (t & 15)*4;
        float4 bv = *(const float4*)(W + (size_t)(k0 + brr)*256 + n0 + bc);
        *(float4*)(Bs + brr*64 + bc) = bv;
        __syncthreads();
        #pragma unroll
        for (int kk = 0; kk < 16; kk++){
            float a[4];
            #pragma unroll
            for (int u = 0; u < 4; u++) a[u] = As[(ty*4 + u)*16 + kk];
            float4 b4 = *(const float4*)(Bs + kk*64 + tx*4);
            #pragma unroll
            for (int u = 0; u < 4; u++){
                acc[u][0] = fmaf(a[u], b4.x, acc[u][0]);
                acc[u][1] = fmaf(a[u], b4.y, acc[u][1]);
                acc[u][2] = fmaf(a[u], b4.z, acc[u][2]);
                acc[u][3] = fmaf(a[u], b4.w, acc[u][3]);
            }
        }
        __syncthreads();
    }
    #pragma unroll
    for (int u = 0; u < 4; u++){
        int r = m0 + ty*4 + u;
        if (r < M){
            #pragma unroll
            for (int v = 0; v < 4; v++){
                int c = n0 + tx*4 + v;
                C[(size_t)r*256 + c] = fmaxf(acc[u][v] + bias[c], 0.f);
            }
        }
    }
}

// ---------------- fused Y = L @ X (both graphs, 64-col chunks) ----------------
__global__ __launch_bounds__(256) void k_Ymat2(const float* __restrict__ Lreeb){
    __shared__ __align__(16) float Ls[64*64];
    __shared__ __align__(16) float Xs[64*64];
    int b = blockIdx.y, t = threadIdx.x, z = blockIdx.z;
    int NR = z ? PP : RR;
    const float* Lb = z ? (g_Lfps + (size_t)b*PP*PP) : (Lreeb + (size_t)b*RR*RR);
    const float* Xb = z ? (g_outf + (size_t)b*PP*CH) : (g_outr + (size_t)b*RR*CH);
    float* Yb       = z ? (g_Yf   + (size_t)b*PP*CH) : (g_Yr   + (size_t)b*RR*CH);
    int c0 = blockIdx.x*64;
    for (int i = t; i < NR*NR; i += 256) Ls[i] = Lb[i];
    for (int i = t; i < NR*64; i += 256){ int n = i >> 6, c = i & 63; Xs[i] = Xb[n*256 + c0 + c]; }
    __syncthreads();
    int tx = t & 15, ty = t >> 4;
    float acc[4][4] = {};
    for (int m = 0; m < NR; m++){
        float4 bv = *(const float4*)(Xs + m*64 + tx*4);
        float a[4];
        #pragma unroll
        for (int u = 0; u < 4; u++){ int n = ty*4 + u; if (n >= NR) n = NR-1; a[u] = Ls[n*NR + m]; }
        #pragma unroll
        for (int u = 0; u < 4; u++){
            acc[u][0] = fmaf(a[u], bv.x, acc[u][0]);
            acc[u][1] = fmaf(a[u], bv.y, acc[u][1]);
            acc[u][2] = fmaf(a[u], bv.z, acc[u][2]);
            acc[u][3] = fmaf(a[u], bv.w, acc[u][3]);
        }
    }
    #pragma unroll
    for (int u = 0; u < 4; u++){
        int n = ty*4 + u;
        if (n < NR){
            #pragma unroll
            for (int v = 0; v < 4; v++) Yb[(size_t)n*256 + c0 + tx*4 + v] = acc[u][v];
        }
    }
}

// ---------------- fused reg2/reg3: M' = X^T Y (64x64 tiles), sumsq partials ----------------
__global__ __launch_bounds__(256) void k_regM2(){
    __shared__ __align__(16) float sX[64*64];
    __shared__ __align__(16) float sY[64*64];
    int zz = blockIdx.z, t = threadIdx.x;
    int b = zz & 31, fps = zz >> 5;
    int NR = fps ? PP : RR;
    const float* Xb = fps ? (g_outf + (size_t)b*PP*CH) : (g_outr + (size_t)b*RR*CH);
    const float* Yb = fps ? (g_Yf   + (size_t)b*PP*CH) : (g_Yr   + (size_t)b*RR*CH);
    float* part     = fps ? g_p3 : g_p2;
    int f0 = blockIdx.x*64, g0 = blockIdx.y*64;
    for (int i = t; i < NR*64; i += 256){
        int n = i >> 6, j = i & 63;
        sX[i] = Xb[n*256 + f0 + j];
        sY[i] = Yb[n*256 + g0 + j];
    }
    __syncthreads();
    int tx = t & 15, ty = t >> 4;
    float acc[4][4] = {};
    for (int n = 0; n < NR; n++){
        float a[4];
        #pragma unroll
        for (int u = 0; u < 4; u++) a[u] = sX[n*64 + ty*4 + u];
        float4 b4 = *(const float4*)(sY + n*64 + tx*4);
        #pragma unroll
        for (int u = 0; u < 4; u++){
            acc[u][0] = fmaf(a[u], b4.x, acc[u][0]);
            acc[u][1] = fmaf(a[u], b4.y, acc[u][1]);
            acc[u][2] = fmaf(a[u], b4.z, acc[u][2]);
            acc[u][3] = fmaf(a[u], b4.w, acc[u][3]);
        }
    }
    float s = 0.f;
    #pragma unroll
    for (int u = 0; u < 4; u++)
        #pragma unroll
        for (int v = 0; v < 4; v++) s = fmaf(acc[u][v], acc[u][v], s);
    s = block_reduce_sum(s);
    if (t == 0) part[(b*4 + blockIdx.y)*4 + blockIdx.x] = s;
}

// ---------------- head: maxpool + fc1 + fc3 (+ regs vector on block 0) ----------------
__global__ __launch_bounds__(256) void k_head(const float* __restrict__ fc1w,
                                              const float* __restrict__ fc1b,
                                              const float* __restrict__ fc3w,
                                              const float* __restrict__ fc3b,
                                              float* __restrict__ out){
    __shared__ float feat[512];
    __shared__ float h[256];
    int b = blockIdx.x, t = threadIdx.x;
    float m = -3.4e38f;
    const float* orb = g_outr + (size_t)b*RR*CH;
    for (int n = 0; n < RR; n++) m = fmaxf(m, orb[n*CH + t]);
    feat[t] = m;
    m = -3.4e38f;
    const float* ofb = g_outf + (size_t)b*PP*CH;
    for (int n = 0; n < PP; n++) m = fmaxf(m, ofb[n*CH + t]);
    feat[256 + t] = m;
    __syncthreads();
    float acc = fc1b[t];
    #pragma unroll 4
    for (int i = 0; i < 512; i++) acc = fmaf(feat[i], fc1w[(size_t)i*256 + t], acc);
    h[t] = fmaxf(acc, 0.f);
    __syncthreads();
    if (t < 40){
        float a = fc3b[t];
        #pragma unroll 4
        for (int o = 0; o < 256; o++) a = fmaf(h[o], fc3w[o*40 + t], a);
        out[b*40 + t] = a;
    }
    if (b == 0){
        float a = 0.f;
        for (int i = t; i < 512; i += 256){ float v = fc1w[(size_t)i*256]; a = fmaf(v, v, a); }
        float r4 = block_reduce_sum(a);
        float c = 0.f;
        { float v = fc3w[t*40]; c = v*v; }
        float r6 = block_reduce_sum(c);
        float p = g_p1p[t];
        float r1 = block_reduce_sum(p);
        p = 0.f;
        for (int i = t; i < 512; i += 256) p += g_p2[i];
        float r2 = block_reduce_sum(p);
        p = 0.f;
        for (int i = t; i < 512; i += 256) p += g_p3[i];
        float r3 = block_reduce_sum(p);
        if (t == 0){
            out[1280] = r1; out[1281] = r2; out[1282] = r3; out[1283] = r4;
            float v1 = fc1b[0]; out[1284] = v1*v1;
            out[1285] = r6;
            float v3 = fc3b[0]; out[1286] = v3*v3;
        }
    }
}

// ---------------- launcher: single stream, no events ----------------
extern "C" void kernel_launch(void* const* d_in, const int* in_sizes, int n_in,
                              void* d_out, int out_size){
    (void)in_sizes; (void)n_in; (void)out_size;
    const float* x     = (const float*)d_in[0];
    const float* Lreeb = (const float*)d_in[2];
    const float* W1    = (const float*)d_in[3];
    const float* b1    = (const float*)d_in[4];
    const float* Wr    = (const float*)d_in[5];
    const float* br    = (const float*)d_in[6];
    const float* Wf    = (const float*)d_in[7];
    const float* bf    = (const float*)d_in[8];
    const float* fc1w  = (const float*)d_in[9];
    const float* fc1b  = (const float*)d_in[10];
    const float* fc3w  = (const float*)d_in[11];
    const float* fc3b  = (const float*)d_in[12];
    const int* sccs    = (const int*)d_in[13];
    const int* sccsf   = (const int*)d_in[14];
    float* out = (float*)d_out;

    int* nbr_p; cudaGetSymbolAddress((void**)&nbr_p, g_nbr);

    k_knn<<<dim3(32, BB), 256>>>(x, nbr_p);
    k_conv1<<<(BB*NN1)/128, 128>>>(x, W1, b1);
    k_Yknn<<<(BB*NN1*32)/256, 256>>>();
    k_reg1a<<<dim3(16, BB), 256>>>();
    k_reg1b<<<dim3(8, BB), 256>>>();
    k_vpool<<<dim3(PP + RR/4, BB), 256>>>(sccsf, sccs);
    k_Lfps<<<BB, 256>>>();
    k_cheb2<<<dim3(4, BB, 2), 256>>>(Lreeb);
    k_gemm2<<<dim3(32, 4, 2), 256>>>(Wr, br, Wf, bf);
    k_Ymat2<<<dim3(4, BB, 2), 256>>>(Lreeb);
    k_regM2<<<dim3(4, 4, 64), 256>>>();
    k_head<<<BB, 256>>>(fc1w, fc1b, fc3w, fc3b, out);
}